// round 6
// baseline (speedup 1.0000x reference)
// R5: resubmission of the R4 fp32 baseline — R4 bench died on broker infra
// ("GB300 container failed twice"), no kernel signal. No code changes.
#include <cuda_runtime.h>
#include <math.h>

#define SEQ    2048
#define DM     2048
#define NHEAD  16
#define QLORA  1536
#define KVLORA 512
#define ROPED  64
#define NOPED  128
#define VD     128
#define QHDIM  192          // ROPED + NOPED
#define KVW    576          // KVLORA + ROPED
#define KVROW  256          // NOPED + VD
#define MASKW  2198         // SEQ + 150
#define NEG_BIG (-1e30f)

// ---------------- scratch (device globals; no allocation allowed) ----------
__device__ float g_qlat[SEQ * QLORA];          // x@Wqa, rmsnorm'd in place
__device__ float g_ckv [SEQ * KVW];            // x@Wkva; cols [0,512) rmsnorm'd in place
__device__ float g_q   [SEQ * NHEAD * QHDIM];  // qn@Wqb
__device__ float g_kv  [SEQ * NHEAD * KVROW];  // ckvn@Wkvb  (k_nope | v per head)
__device__ float g_Qh  [NHEAD * SEQ * QHDIM];  // per-head query, [pe|nope], rope applied
__device__ float g_Kh  [NHEAD * SEQ * QHDIM];  // per-head key,   [pe|nope], rope applied
__device__ float g_ao  [SEQ * DM];             // attention output (heads concat)

// ---------------- generic fp32 SGEMM: C[M,N] = A[M,K] @ B[K,N] -------------
// 128x128 block tile, 8x8 per thread, BK=8, 256 threads. Row-major, lda/ldb/ldc.
// Requires: M % 128 == 0, K % 8 == 0, N % 4 == 0 (ragged N handled via guards).
__global__ void __launch_bounds__(256) sgemm(
    const float* __restrict__ A, const float* __restrict__ B, float* __restrict__ C,
    int M, int N, int K, int lda, int ldb, int ldc)
{
    __shared__ float As[8][128];
    __shared__ float Bs[8][128];

    const int tid = threadIdx.x;
    const int tx = tid & 15;        // 0..15 -> N direction
    const int ty = tid >> 4;        // 0..15 -> M direction
    const int row0 = blockIdx.y * 128;
    const int col0 = blockIdx.x * 128;

    // A load: thread -> (row = tid/2, k-chunk = (tid&1)*4)
    const int ar  = tid >> 1;
    const int ak4 = (tid & 1) * 4;
    // B load: thread -> (k = tid/32, col-chunk = (tid&31)*4)
    const int bk  = tid >> 5;
    const int bc  = (tid & 31) * 4;

    float acc[8][8];
    #pragma unroll
    for (int i = 0; i < 8; i++)
        #pragma unroll
        for (int j = 0; j < 8; j++) acc[i][j] = 0.f;

    for (int k0 = 0; k0 < K; k0 += 8) {
        float4 av = *(const float4*)(A + (size_t)(row0 + ar) * lda + k0 + ak4);
        As[ak4 + 0][ar] = av.x;
        As[ak4 + 1][ar] = av.y;
        As[ak4 + 2][ar] = av.z;
        As[ak4 + 3][ar] = av.w;

        if (col0 + bc < N) {
            *(float4*)&Bs[bk][bc] = *(const float4*)(B + (size_t)(k0 + bk) * ldb + col0 + bc);
        } else {
            *(float4*)&Bs[bk][bc] = make_float4(0.f, 0.f, 0.f, 0.f);
        }
        __syncthreads();

        #pragma unroll
        for (int kk = 0; kk < 8; kk++) {
            float4 a0 = *(const float4*)&As[kk][ty * 8];
            float4 a1 = *(const float4*)&As[kk][ty * 8 + 4];
            float4 b0 = *(const float4*)&Bs[kk][tx * 8];
            float4 b1 = *(const float4*)&Bs[kk][tx * 8 + 4];
            float a[8] = {a0.x, a0.y, a0.z, a0.w, a1.x, a1.y, a1.z, a1.w};
            float b[8] = {b0.x, b0.y, b0.z, b0.w, b1.x, b1.y, b1.z, b1.w};
            #pragma unroll
            for (int i = 0; i < 8; i++)
                #pragma unroll
                for (int j = 0; j < 8; j++) acc[i][j] += a[i] * b[j];
        }
        __syncthreads();
    }

    #pragma unroll
    for (int i = 0; i < 8; i++) {
        int r = row0 + ty * 8 + i;
        #pragma unroll
        for (int j = 0; j < 8; j++) {
            int c = col0 + tx * 8 + j;
            if (c < N) C[(size_t)r * ldc + c] = acc[i][j];
        }
    }
}

// ---------------- in-place RMSNorm over first W cols of each row -----------
__global__ void __launch_bounds__(256) rmsnorm_kernel(
    float* __restrict__ data, const float* __restrict__ w, int W, int ld)
{
    const int row = blockIdx.x;
    float* p = data + (size_t)row * ld;
    float ss = 0.f;
    for (int c = threadIdx.x; c < W; c += 256) { float v = p[c]; ss += v * v; }
    __shared__ float red[256];
    red[threadIdx.x] = ss;
    __syncthreads();
    #pragma unroll
    for (int s = 128; s > 0; s >>= 1) {
        if (threadIdx.x < s) red[threadIdx.x] += red[threadIdx.x + s];
        __syncthreads();
    }
    float scale = rsqrtf(red[0] / (float)W + 1e-6f);
    for (int c = threadIdx.x; c < W; c += 256) p[c] = w[c] * (p[c] * scale);
}

// ---------------- build per-head Q/K with rope, layout [pe|nope] -----------
__global__ void __launch_bounds__(256) build_qk(const float* __restrict__ freqs)
{
    const int s = blockIdx.x;
    const int tid = threadIdx.x;
    __shared__ float cs[32], sn[32];
    if (tid < 32) {
        cs[tid] = freqs[(s * 32 + tid) * 2 + 0];
        sn[tid] = freqs[(s * 32 + tid) * 2 + 1];
    }
    __syncthreads();

    const float* qrow = g_q + (size_t)s * NHEAD * QHDIM;
    for (int idx = tid; idx < NHEAD * QHDIM; idx += 256) {
        int hh = idx / QHDIM, d = idx % QHDIM;
        float val;
        if (d < ROPED) {
            int j = d >> 1;
            float a = qrow[hh * QHDIM + NOPED + 2 * j];
            float b = qrow[hh * QHDIM + NOPED + 2 * j + 1];
            val = (d & 1) ? (a * sn[j] + b * cs[j]) : (a * cs[j] - b * sn[j]);
        } else {
            val = qrow[hh * QHDIM + (d - ROPED)];
        }
        g_Qh[((size_t)hh * SEQ + s) * QHDIM + d] = val;
    }

    const float* kperow = g_ckv + (size_t)s * KVW + KVLORA;   // raw (pre-norm) k_pe
    const float* kvrow  = g_kv  + (size_t)s * NHEAD * KVROW;
    for (int idx = tid; idx < NHEAD * QHDIM; idx += 256) {
        int hh = idx / QHDIM, d = idx % QHDIM;
        float val;
        if (d < ROPED) {
            int j = d >> 1;
            float a = kperow[2 * j], b = kperow[2 * j + 1];
            val = (d & 1) ? (a * sn[j] + b * cs[j]) : (a * cs[j] - b * sn[j]);
        } else {
            val = kvrow[hh * KVROW + (d - ROPED)];
        }
        g_Kh[((size_t)hh * SEQ + s) * QHDIM + d] = val;
    }
}

// ---------------- flash attention: per (head, 64-row Q block) --------------
// smem (floats): Qt[192][64] | Kt[192][64] | Vs[64][128] | Ss[64][68] | m/l/a[64]
#define QT_OFF 0
#define KT_OFF 12288
#define VS_OFF 24576
#define SS_OFF 32768
#define RM_OFF 37120
#define RL_OFF 37184
#define RA_OFF 37248
#define FLASH_SMEM_BYTES (37312 * 4)

__global__ void __launch_bounds__(256) flash_kernel(
    const int* __restrict__ mask, float* __restrict__ ao)
{
    extern __shared__ float smf[];
    float* Qt   = smf + QT_OFF;
    float* Kt   = smf + KT_OFF;
    float* Vs   = smf + VS_OFF;
    float* Ss   = smf + SS_OFF;
    float* rowm = smf + RM_OFF;
    float* rowl = smf + RL_OFF;
    float* rowa = smf + RA_OFF;

    const int tid = threadIdx.x;
    const int tx = tid & 15;
    const int ty = tid >> 4;
    const int qb = blockIdx.x;
    const int h  = blockIdx.y;
    const float scale = 0.088388347648318447f;   // 1/sqrt(HEAD_DIM=128)

    // load Q tile transposed: Qt[k][r]
    const float* Qg = g_Qh + ((size_t)h * SEQ + qb * 64) * QHDIM;
    for (int i = tid; i < 64 * 48; i += 256) {
        int r = i / 48, c4 = (i % 48) * 4;
        float4 v = *(const float4*)(Qg + (size_t)r * QHDIM + c4);
        Qt[(c4 + 0) * 64 + r] = v.x;
        Qt[(c4 + 1) * 64 + r] = v.y;
        Qt[(c4 + 2) * 64 + r] = v.z;
        Qt[(c4 + 3) * 64 + r] = v.w;
    }
    if (tid < 64) { rowm[tid] = NEG_BIG; rowl[tid] = 0.f; }

    float o[4][8];
    #pragma unroll
    for (int i = 0; i < 4; i++)
        #pragma unroll
        for (int j = 0; j < 8; j++) o[i][j] = 0.f;
    __syncthreads();

    for (int kb = 0; kb < SEQ / 64; kb++) {
        // K tile transposed
        const float* Kg = g_Kh + ((size_t)h * SEQ + kb * 64) * QHDIM;
        for (int i = tid; i < 64 * 48; i += 256) {
            int r = i / 48, c4 = (i % 48) * 4;
            float4 v = *(const float4*)(Kg + (size_t)r * QHDIM + c4);
            Kt[(c4 + 0) * 64 + r] = v.x;
            Kt[(c4 + 1) * 64 + r] = v.y;
            Kt[(c4 + 2) * 64 + r] = v.z;
            Kt[(c4 + 3) * 64 + r] = v.w;
        }
        // V tile (row-major)
        const float* Vg = g_kv + (size_t)(kb * 64) * (NHEAD * KVROW) + h * KVROW + NOPED;
        for (int i = tid; i < 64 * 32; i += 256) {
            int r = i >> 5, c4 = (i & 31) * 4;
            *(float4*)(Vs + r * 128 + c4) =
                *(const float4*)(Vg + (size_t)r * (NHEAD * KVROW) + c4);
        }
        __syncthreads();

        // S = (Q K^T) * scale
        float acc[4][4];
        #pragma unroll
        for (int i = 0; i < 4; i++)
            #pragma unroll
            for (int j = 0; j < 4; j++) acc[i][j] = 0.f;
        #pragma unroll 4
        for (int k = 0; k < QHDIM; k++) {
            float4 a = *(const float4*)(Qt + k * 64 + ty * 4);
            float4 b = *(const float4*)(Kt + k * 64 + tx * 4);
            float av[4] = {a.x, a.y, a.z, a.w};
            float bv[4] = {b.x, b.y, b.z, b.w};
            #pragma unroll
            for (int i = 0; i < 4; i++)
                #pragma unroll
                for (int j = 0; j < 4; j++) acc[i][j] += av[i] * bv[j];
        }
        #pragma unroll
        for (int i = 0; i < 4; i++) {
            float4 s4 = make_float4(acc[i][0] * scale, acc[i][1] * scale,
                                    acc[i][2] * scale, acc[i][3] * scale);
            *(float4*)(Ss + (ty * 4 + i) * 68 + tx * 4) = s4;
        }
        __syncthreads();

        // online softmax (one thread per row)
        if (tid < 64) {
            const int* mrow = mask + (size_t)(qb * 64 + tid) * MASKW + 150 + kb * 64;
            float* srow = Ss + tid * 68;
            float mx = rowm[tid];
            float nm = mx;
            for (int c = 0; c < 64; c++) {
                float v = srow[c];
                if (mrow[c] == 1) { v = NEG_BIG; srow[c] = v; }
                nm = fmaxf(nm, v);
            }
            float alpha = __expf(mx - nm);
            float s = 0.f;
            for (int c = 0; c < 64; c++) {
                float p = __expf(srow[c] - nm);
                srow[c] = p;
                s += p;
            }
            rowm[tid] = nm;
            rowl[tid] = rowl[tid] * alpha + s;
            rowa[tid] = alpha;
        }
        __syncthreads();

        // O = O*alpha + P @ V
        #pragma unroll
        for (int i = 0; i < 4; i++) {
            float al = rowa[ty * 4 + i];
            #pragma unroll
            for (int j = 0; j < 8; j++) o[i][j] *= al;
        }
        #pragma unroll 2
        for (int kk = 0; kk < 64; kk++) {
            float p[4];
            #pragma unroll
            for (int i = 0; i < 4; i++) p[i] = Ss[(ty * 4 + i) * 68 + kk];
            float4 v0 = *(const float4*)(Vs + kk * 128 + tx * 8);
            float4 v1 = *(const float4*)(Vs + kk * 128 + tx * 8 + 4);
            float vv[8] = {v0.x, v0.y, v0.z, v0.w, v1.x, v1.y, v1.z, v1.w};
            #pragma unroll
            for (int i = 0; i < 4; i++)
                #pragma unroll
                for (int j = 0; j < 8; j++) o[i][j] += p[i] * vv[j];
        }
        __syncthreads();
    }

    #pragma unroll
    for (int i = 0; i < 4; i++) {
        float inv = 1.f / rowl[ty * 4 + i];
        int r = qb * 64 + ty * 4 + i;
        #pragma unroll
        for (int j = 0; j < 8; j++)
            ao[(size_t)r * DM + h * VD + tx * 8 + j] = o[i][j] * inv;
    }
}

// ---------------------------------------------------------------------------
extern "C" void kernel_launch(void* const* d_in, const int* in_sizes, int n_in,
                              void* d_out, int out_size)
{
    const float* x     = (const float*)d_in[0];
    const int*   mask  = (const int*)  d_in[1];
    const float* freqs = (const float*)d_in[2];
    const float* Wqa   = (const float*)d_in[3];
    const float* qln   = (const float*)d_in[4];
    const float* Wqb   = (const float*)d_in[5];
    const float* Wkva  = (const float*)d_in[6];
    const float* kvln  = (const float*)d_in[7];
    const float* Wkvb  = (const float*)d_in[8];
    const float* Wo    = (const float*)d_in[9];
    float* out = (float*)d_out;

    float *qlat, *ckv, *q, *kv, *ao;
    cudaGetSymbolAddress((void**)&qlat, g_qlat);
    cudaGetSymbolAddress((void**)&ckv,  g_ckv);
    cudaGetSymbolAddress((void**)&q,    g_q);
    cudaGetSymbolAddress((void**)&kv,   g_kv);
    cudaGetSymbolAddress((void**)&ao,   g_ao);

    dim3 blk(256);

    // 1) qlat = x @ Wqa                      [2048,2048]x[2048,1536]
    sgemm<<<dim3(QLORA / 128, SEQ / 128), blk>>>(x, Wqa, qlat,
        SEQ, QLORA, DM, DM, QLORA, QLORA);
    // 2) ckv = x @ Wkva                      [2048,2048]x[2048,576]
    sgemm<<<dim3((KVW + 127) / 128, SEQ / 128), blk>>>(x, Wkva, ckv,
        SEQ, KVW, DM, DM, KVW, KVW);
    // 3) rmsnorm(qlat, qln) in place
    rmsnorm_kernel<<<SEQ, 256>>>(qlat, qln, QLORA, QLORA);
    // 4) rmsnorm(ckv[:, :512], kvln) in place (k_pe cols 512..575 untouched)
    rmsnorm_kernel<<<SEQ, 256>>>(ckv, kvln, KVLORA, KVW);
    // 5) q = qlat_n @ Wqb                    [2048,1536]x[1536,3072]
    sgemm<<<dim3((NHEAD * QHDIM) / 128, SEQ / 128), blk>>>(qlat, Wqb, q,
        SEQ, NHEAD * QHDIM, QLORA, QLORA, NHEAD * QHDIM, NHEAD * QHDIM);
    // 6) kv = ckv_n @ Wkvb                   [2048,512(ld576)]x[512,4096]
    sgemm<<<dim3((NHEAD * KVROW) / 128, SEQ / 128), blk>>>(ckv, Wkvb, kv,
        SEQ, NHEAD * KVROW, KVLORA, KVW, NHEAD * KVROW, NHEAD * KVROW);
    // 7) rope + per-head layout
    build_qk<<<SEQ, 256>>>(freqs);
    // 8) flash attention -> ao[s, h*128+d]
    cudaFuncSetAttribute(flash_kernel,
                         cudaFuncAttributeMaxDynamicSharedMemorySize, FLASH_SMEM_BYTES);
    flash_kernel<<<dim3(SEQ / 64, NHEAD), blk, FLASH_SMEM_BYTES>>>(mask, ao);
    // 9) out = ao @ Wo                       [2048,2048]x[2048,2048]
    sgemm<<<dim3(DM / 128, SEQ / 128), blk>>>(ao, Wo, out,
        SEQ, DM, DM, DM, DM, DM);
}

// round 8
// speedup vs baseline: 1.3197x; 1.3197x over previous
// R7: mma.sync (HMMA) split-precision bf16 GEMMs — tcgen05 is rejected because
// the harness targets plain sm_103 (no 'a' suffix). Flash attn still SIMT fp32.
// Best passing: R5 fp32 baseline 4786.7us.
#include <cuda_runtime.h>
#include <cuda_bf16.h>
#include <math.h>
#include <stdint.h>

#define SEQ    2048
#define DM     2048
#define NHEAD  16
#define QLORA  1536
#define KVLORA 512
#define ROPED  64
#define NOPED  128
#define VD     128
#define QHDIM  192
#define KVW    576
#define KVROW  256
#define MASKW  2198
#define NEG_BIG (-1e30f)

#define NQ   (NHEAD * QHDIM)   // 3072
#define NKV  (NHEAD * KVROW)   // 4096
#define KVWP 640               // Wkva transposed, padded N

// ---------------- fp32 scratch ----------------
__device__ float g_qlat[SEQ * QLORA];
__device__ float g_ckv [SEQ * KVW];
__device__ float g_q   [SEQ * NQ];
__device__ float g_kv  [SEQ * NKV];
__device__ float g_Qh  [NHEAD * SEQ * QHDIM];
__device__ float g_Kh  [NHEAD * SEQ * QHDIM];
__device__ float g_ao  [SEQ * DM];

// ---------------- bf16 hi/lo split buffers ----------------
__device__ unsigned short g_xh [SEQ * DM],    g_xl [SEQ * DM];
__device__ unsigned short g_qlh[SEQ * QLORA], g_qll[SEQ * QLORA];
__device__ unsigned short g_ckh[SEQ * KVW],   g_ckl[SEQ * KVW];
__device__ unsigned short g_aoh[SEQ * DM],    g_aol[SEQ * DM];
// weights transposed to [N(pad), K] K-major (B^T, row-major over N)
__device__ unsigned short g_WqaTh [QLORA * DM],  g_WqaTl [QLORA * DM];
__device__ unsigned short g_WkvaTh[KVWP  * DM],  g_WkvaTl[KVWP  * DM];
__device__ unsigned short g_WqbTh [NQ * QLORA],  g_WqbTl [NQ * QLORA];
__device__ unsigned short g_WkvbTh[NKV * KVLORA],g_WkvbTl[NKV * KVLORA];
__device__ unsigned short g_WoTh  [DM * DM],     g_WoTl  [DM * DM];

// ======================= PTX helpers (baseline sm_80+ features only) =======
__device__ __forceinline__ uint32_t smem_u32(const void* p) {
    uint32_t a;
    asm("{ .reg .u64 t; cvta.to.shared.u64 t, %1; cvt.u32.u64 %0, t; }"
        : "=r"(a) : "l"(p));
    return a;
}
__device__ __forceinline__ void ldm_x4(uint32_t* r, uint32_t a) {
    asm volatile("ldmatrix.sync.aligned.m8n8.x4.shared.b16 {%0,%1,%2,%3}, [%4];"
        : "=r"(r[0]), "=r"(r[1]), "=r"(r[2]), "=r"(r[3]) : "r"(a));
}
__device__ __forceinline__ void mma16816(float* c, const uint32_t* a, const uint32_t* b) {
    asm volatile(
        "mma.sync.aligned.m16n8k16.row.col.f32.bf16.bf16.f32 "
        "{%0,%1,%2,%3}, {%4,%5,%6,%7}, {%8,%9}, {%0,%1,%2,%3};"
        : "+f"(c[0]), "+f"(c[1]), "+f"(c[2]), "+f"(c[3])
        : "r"(a[0]), "r"(a[1]), "r"(a[2]), "r"(a[3]), "r"(b[0]), "r"(b[1]));
}

// ======================= prep kernels =======================
__global__ void __launch_bounds__(256) split2(
    const float* __restrict__ src, unsigned short* __restrict__ h,
    unsigned short* __restrict__ l, int n)
{
    int i = blockIdx.x * 256 + threadIdx.x;
    if (i < n) {
        float v = src[i];
        __nv_bfloat16 hh = __float2bfloat16(v);
        __nv_bfloat16 ll = __float2bfloat16(v - __bfloat162float(hh));
        h[i] = __bfloat16_as_ushort(hh);
        l[i] = __bfloat16_as_ushort(ll);
    }
}

// W[K,N] fp32 row-major -> Th/Tl [Npad, K] bf16 (rows n>=N zero-filled)
__global__ void __launch_bounds__(256) transpose_split(
    const float* __restrict__ W, unsigned short* __restrict__ Th,
    unsigned short* __restrict__ Tl, int K, int N)
{
    __shared__ float t[32][33];
    int n0 = blockIdx.x * 32, k0 = blockIdx.y * 32;
    int tx = threadIdx.x & 31, ty = threadIdx.x >> 5;   // 32 x 8
    #pragma unroll
    for (int i = 0; i < 4; i++) {
        int k = k0 + ty + i * 8, n = n0 + tx;
        t[ty + i * 8][tx] = (n < N) ? W[(size_t)k * N + n] : 0.f;
    }
    __syncthreads();
    #pragma unroll
    for (int i = 0; i < 4; i++) {
        int n = n0 + ty + i * 8, k = k0 + tx;
        float v = t[tx][ty + i * 8];
        __nv_bfloat16 hh = __float2bfloat16(v);
        __nv_bfloat16 ll = __float2bfloat16(v - __bfloat162float(hh));
        Th[(size_t)n * K + k] = __bfloat16_as_ushort(hh);
        Tl[(size_t)n * K + k] = __bfloat16_as_ushort(ll);
    }
}

// ======================= HMMA split GEMM =======================
// C[M,N] = (Ah+Al)[M,K] @ (Bh+Bl)^T, B stored [Npad,K] K-major.
// 128x128 CTA tile, 8 warps = 2(m)x4(n), warp tile 64x32, BK=32, double-buffered.
// smem row stride 80B (32 bf16 + 16B pad) -> conflict-free ldmatrix.
#define T_STRIDE_US 40          // ushorts per row (80B)
#define TEN_US      (128 * 40)  // 5120 ushorts = 10240 B per tensor tile
#define STAGE_US    (4 * TEN_US)
#define GEMM_SMEM   (2 * STAGE_US * 2)   // bytes = 81920

__global__ void __launch_bounds__(256) gemm_mma(
    const unsigned short* __restrict__ Ahp, const unsigned short* __restrict__ Alp, int lda,
    const unsigned short* __restrict__ Bhp, const unsigned short* __restrict__ Blp, int ldb,
    float* __restrict__ C, int ldc, int N, int K)
{
    extern __shared__ unsigned short smus[];
    const uint32_t sbase = smem_u32(smus);
    const int tid  = threadIdx.x;
    const int lane = tid & 31;
    const int wid  = tid >> 5;
    const int wm   = wid & 1;        // 0..1 (m)
    const int wn   = wid >> 1;       // 0..3 (n)
    const int row0 = blockIdx.y * 128;
    const int col0 = blockIdx.x * 128;

    const unsigned short* bases[4] = { Ahp, Alp, Bhp, Blp };
    const int ldv[4] = { lda, lda, ldb, ldb };
    const int rbv[4] = { row0, row0, col0, col0 };

    float acc[4][4][4];
    #pragma unroll
    for (int i = 0; i < 4; i++)
        #pragma unroll
        for (int j = 0; j < 4; j++)
            #pragma unroll
            for (int q = 0; q < 4; q++) acc[i][j][q] = 0.f;

    const int NC = K >> 5;

    // ldmatrix source addresses (fixed per thread, add stage/tensor/k offsets)
    const int a_r  = lane & 15;            // A: row within 16-row frag
    const int a_c  = (lane >> 4) * 16;     // A: 16B half select
    const int b_q  = lane >> 3;            // B: quad 0..3
    const int b_r  = lane & 7;             // B: row within 8
    const uint32_t aoff = (uint32_t)((wm * 64 + a_r) * 80 + a_c);
    const uint32_t boff = (uint32_t)((wn * 32 + (b_q >> 1) * 8 + b_r) * 80 + (b_q & 1) * 16);

    // preload chunk 0 into stage 0
    {
        const int k0 = 0;
        #pragma unroll
        for (int t = 0; t < 4; t++)
            #pragma unroll
            for (int i = 0; i < 2; i++) {
                int w = tid + i * 256;
                int r = w >> 2, c16 = w & 3;
                uint4 v = *(const uint4*)(bases[t] + (size_t)(rbv[t] + r) * ldv[t] + k0 + c16 * 8);
                *(uint4*)(smus + t * TEN_US + r * T_STRIDE_US + c16 * 8) = v;
            }
    }
    __syncthreads();

    for (int c = 0; c < NC; c++) {
        const int s = c & 1;
        // prefetch next chunk into other stage (LDG issued before compute)
        if (c + 1 < NC) {
            const int k0 = (c + 1) << 5;
            #pragma unroll
            for (int t = 0; t < 4; t++)
                #pragma unroll
                for (int i = 0; i < 2; i++) {
                    int w = tid + i * 256;
                    int r = w >> 2, c16 = w & 3;
                    uint4 v = *(const uint4*)(bases[t] + (size_t)(rbv[t] + r) * ldv[t] + k0 + c16 * 8);
                    *(uint4*)(smus + (s ^ 1) * STAGE_US + t * TEN_US + r * T_STRIDE_US + c16 * 8) = v;
                }
        }

        const uint32_t st = sbase + (uint32_t)s * (STAGE_US * 2);   // bytes
        #pragma unroll
        for (int ks = 0; ks < 2; ks++) {
            const uint32_t kb = (uint32_t)(ks * 32);
            uint32_t Ah[4][4], Al[4][4], Bh[4][2], Bl[4][2];
            #pragma unroll
            for (int mf = 0; mf < 4; mf++) {
                ldm_x4(Ah[mf], st + 0          + aoff + (uint32_t)(mf * 16 * 80) + kb);
                ldm_x4(Al[mf], st + TEN_US * 2 + aoff + (uint32_t)(mf * 16 * 80) + kb);
            }
            #pragma unroll
            for (int np = 0; np < 2; np++) {
                uint32_t rh[4], rl[4];
                ldm_x4(rh, st + TEN_US * 4 + boff + (uint32_t)(np * 16 * 80) + kb);
                ldm_x4(rl, st + TEN_US * 6 + boff + (uint32_t)(np * 16 * 80) + kb);
                Bh[np * 2][0] = rh[0]; Bh[np * 2][1] = rh[1];
                Bh[np * 2 + 1][0] = rh[2]; Bh[np * 2 + 1][1] = rh[3];
                Bl[np * 2][0] = rl[0]; Bl[np * 2][1] = rl[1];
                Bl[np * 2 + 1][0] = rl[2]; Bl[np * 2 + 1][1] = rl[3];
            }
            #pragma unroll
            for (int mf = 0; mf < 4; mf++)
                #pragma unroll
                for (int nf = 0; nf < 4; nf++) {
                    mma16816(acc[mf][nf], Ah[mf], Bh[nf]);
                    mma16816(acc[mf][nf], Ah[mf], Bl[nf]);
                    mma16816(acc[mf][nf], Al[mf], Bh[nf]);
                }
        }
        __syncthreads();
    }

    // epilogue
    #pragma unroll
    for (int mf = 0; mf < 4; mf++) {
        int r0 = row0 + wm * 64 + mf * 16 + (lane >> 2);
        #pragma unroll
        for (int nf = 0; nf < 4; nf++) {
            int c0 = col0 + wn * 32 + nf * 8 + (lane & 3) * 2;
            if (c0 < N) {
                C[(size_t)r0 * ldc + c0] = acc[mf][nf][0];
                C[(size_t)(r0 + 8) * ldc + c0] = acc[mf][nf][2];
            }
            if (c0 + 1 < N) {
                C[(size_t)r0 * ldc + c0 + 1] = acc[mf][nf][1];
                C[(size_t)(r0 + 8) * ldc + c0 + 1] = acc[mf][nf][3];
            }
        }
    }
}

// ======================= rmsnorm =======================
__global__ void __launch_bounds__(256) rmsnorm_kernel(
    float* __restrict__ data, const float* __restrict__ w, int W, int ld)
{
    const int row = blockIdx.x;
    float* p = data + (size_t)row * ld;
    float ss = 0.f;
    for (int c = threadIdx.x; c < W; c += 256) { float v = p[c]; ss += v * v; }
    __shared__ float red[256];
    red[threadIdx.x] = ss;
    __syncthreads();
    #pragma unroll
    for (int s = 128; s > 0; s >>= 1) {
        if (threadIdx.x < s) red[threadIdx.x] += red[threadIdx.x + s];
        __syncthreads();
    }
    float scale = rsqrtf(red[0] / (float)W + 1e-6f);
    for (int c = threadIdx.x; c < W; c += 256) p[c] = w[c] * (p[c] * scale);
}

// ======================= rope + per-head layout =======================
__global__ void __launch_bounds__(256) build_qk(const float* __restrict__ freqs)
{
    const int s = blockIdx.x;
    const int tid = threadIdx.x;
    __shared__ float cs[32], sn[32];
    if (tid < 32) {
        cs[tid] = freqs[(s * 32 + tid) * 2 + 0];
        sn[tid] = freqs[(s * 32 + tid) * 2 + 1];
    }
    __syncthreads();

    const float* qrow = g_q + (size_t)s * NQ;
    for (int idx = tid; idx < NQ; idx += 256) {
        int hh = idx / QHDIM, d = idx % QHDIM;
        float val;
        if (d < ROPED) {
            int j = d >> 1;
            float a = qrow[hh * QHDIM + NOPED + 2 * j];
            float b = qrow[hh * QHDIM + NOPED + 2 * j + 1];
            val = (d & 1) ? (a * sn[j] + b * cs[j]) : (a * cs[j] - b * sn[j]);
        } else {
            val = qrow[hh * QHDIM + (d - ROPED)];
        }
        g_Qh[((size_t)hh * SEQ + s) * QHDIM + d] = val;
    }

    const float* kperow = g_ckv + (size_t)s * KVW + KVLORA;
    const float* kvrow  = g_kv  + (size_t)s * NKV;
    for (int idx = tid; idx < NQ; idx += 256) {
        int hh = idx / QHDIM, d = idx % QHDIM;
        float val;
        if (d < ROPED) {
            int j = d >> 1;
            float a = kperow[2 * j], b = kperow[2 * j + 1];
            val = (d & 1) ? (a * sn[j] + b * cs[j]) : (a * cs[j] - b * sn[j]);
        } else {
            val = kvrow[hh * KVROW + (d - ROPED)];
        }
        g_Kh[((size_t)hh * SEQ + s) * QHDIM + d] = val;
    }
}

// ======================= flash attention (unchanged from R5) ===============
#define QT_OFF 0
#define KT_OFF 12288
#define VS_OFF 24576
#define SS_OFF 32768
#define RM_OFF 37120
#define RL_OFF 37184
#define RA_OFF 37248
#define FLASH_SMEM_BYTES (37312 * 4)

__global__ void __launch_bounds__(256) flash_kernel(
    const int* __restrict__ mask, float* __restrict__ ao)
{
    extern __shared__ float smf[];
    float* Qt   = smf + QT_OFF;
    float* Kt   = smf + KT_OFF;
    float* Vs   = smf + VS_OFF;
    float* Ss   = smf + SS_OFF;
    float* rowm = smf + RM_OFF;
    float* rowl = smf + RL_OFF;
    float* rowa = smf + RA_OFF;

    const int tid = threadIdx.x;
    const int tx = tid & 15;
    const int ty = tid >> 4;
    const int qb = blockIdx.x;
    const int h  = blockIdx.y;
    const float scale = 0.088388347648318447f;

    const float* Qg = g_Qh + ((size_t)h * SEQ + qb * 64) * QHDIM;
    for (int i = tid; i < 64 * 48; i += 256) {
        int r = i / 48, c4 = (i % 48) * 4;
        float4 v = *(const float4*)(Qg + (size_t)r * QHDIM + c4);
        Qt[(c4 + 0) * 64 + r] = v.x;
        Qt[(c4 + 1) * 64 + r] = v.y;
        Qt[(c4 + 2) * 64 + r] = v.z;
        Qt[(c4 + 3) * 64 + r] = v.w;
    }
    if (tid < 64) { rowm[tid] = NEG_BIG; rowl[tid] = 0.f; }

    float o[4][8];
    #pragma unroll
    for (int i = 0; i < 4; i++)
        #pragma unroll
        for (int j = 0; j < 8; j++) o[i][j] = 0.f;
    __syncthreads();

    for (int kb = 0; kb < SEQ / 64; kb++) {
        const float* Kg = g_Kh + ((size_t)h * SEQ + kb * 64) * QHDIM;
        for (int i = tid; i < 64 * 48; i += 256) {
            int r = i / 48, c4 = (i % 48) * 4;
            float4 v = *(const float4*)(Kg + (size_t)r * QHDIM + c4);
            Kt[(c4 + 0) * 64 + r] = v.x;
            Kt[(c4 + 1) * 64 + r] = v.y;
            Kt[(c4 + 2) * 64 + r] = v.z;
            Kt[(c4 + 3) * 64 + r] = v.w;
        }
        const float* Vg = g_kv + (size_t)(kb * 64) * NKV + h * KVROW + NOPED;
        for (int i = tid; i < 64 * 32; i += 256) {
            int r = i >> 5, c4 = (i & 31) * 4;
            *(float4*)(Vs + r * 128 + c4) =
                *(const float4*)(Vg + (size_t)r * NKV + c4);
        }
        __syncthreads();

        float acc[4][4];
        #pragma unroll
        for (int i = 0; i < 4; i++)
            #pragma unroll
            for (int j = 0; j < 4; j++) acc[i][j] = 0.f;
        #pragma unroll 4
        for (int k = 0; k < QHDIM; k++) {
            float4 a = *(const float4*)(Qt + k * 64 + ty * 4);
            float4 b = *(const float4*)(Kt + k * 64 + tx * 4);
            float av[4] = {a.x, a.y, a.z, a.w};
            float bv[4] = {b.x, b.y, b.z, b.w};
            #pragma unroll
            for (int i = 0; i < 4; i++)
                #pragma unroll
                for (int j = 0; j < 4; j++) acc[i][j] += av[i] * bv[j];
        }
        #pragma unroll
        for (int i = 0; i < 4; i++) {
            float4 s4 = make_float4(acc[i][0] * scale, acc[i][1] * scale,
                                    acc[i][2] * scale, acc[i][3] * scale);
            *(float4*)(Ss + (ty * 4 + i) * 68 + tx * 4) = s4;
        }
        __syncthreads();

        if (tid < 64) {
            const int* mrow = mask + (size_t)(qb * 64 + tid) * MASKW + 150 + kb * 64;
            float* srow = Ss + tid * 68;
            float mx = rowm[tid];
            float nm = mx;
            for (int c = 0; c < 64; c++) {
                float v = srow[c];
                if (mrow[c] == 1) { v = NEG_BIG; srow[c] = v; }
                nm = fmaxf(nm, v);
            }
            float alpha = __expf(mx - nm);
            float s = 0.f;
            for (int c = 0; c < 64; c++) {
                float p = __expf(srow[c] - nm);
                srow[c] = p;
                s += p;
            }
            rowm[tid] = nm;
            rowl[tid] = rowl[tid] * alpha + s;
            rowa[tid] = alpha;
        }
        __syncthreads();

        #pragma unroll
        for (int i = 0; i < 4; i++) {
            float al = rowa[ty * 4 + i];
            #pragma unroll
            for (int j = 0; j < 8; j++) o[i][j] *= al;
        }
        #pragma unroll 2
        for (int kk = 0; kk < 64; kk++) {
            float p[4];
            #pragma unroll
            for (int i = 0; i < 4; i++) p[i] = Ss[(ty * 4 + i) * 68 + kk];
            float4 v0 = *(const float4*)(Vs + kk * 128 + tx * 8);
            float4 v1 = *(const float4*)(Vs + kk * 128 + tx * 8 + 4);
            float vv[8] = {v0.x, v0.y, v0.z, v0.w, v1.x, v1.y, v1.z, v1.w};
            #pragma unroll
            for (int i = 0; i < 4; i++)
                #pragma unroll
                for (int j = 0; j < 8; j++) o[i][j] += p[i] * vv[j];
        }
        __syncthreads();
    }

    #pragma unroll
    for (int i = 0; i < 4; i++) {
        float inv = 1.f / rowl[ty * 4 + i];
        int r = qb * 64 + ty * 4 + i;
        #pragma unroll
        for (int j = 0; j < 8; j++)
            ao[(size_t)r * DM + h * VD + tx * 8 + j] = o[i][j] * inv;
    }
}

// ---------------------------------------------------------------------------
extern "C" void kernel_launch(void* const* d_in, const int* in_sizes, int n_in,
                              void* d_out, int out_size)
{
    const float* x     = (const float*)d_in[0];
    const int*   mask  = (const int*)  d_in[1];
    const float* freqs = (const float*)d_in[2];
    const float* Wqa   = (const float*)d_in[3];
    const float* qln   = (const float*)d_in[4];
    const float* Wqb   = (const float*)d_in[5];
    const float* Wkva  = (const float*)d_in[6];
    const float* kvln  = (const float*)d_in[7];
    const float* Wkvb  = (const float*)d_in[8];
    const float* Wo    = (const float*)d_in[9];
    float* out = (float*)d_out;

    float *qlat, *ckv, *kv, *ao, *qbuf;
    cudaGetSymbolAddress((void**)&qlat, g_qlat);
    cudaGetSymbolAddress((void**)&ckv,  g_ckv);
    cudaGetSymbolAddress((void**)&kv,   g_kv);
    cudaGetSymbolAddress((void**)&ao,   g_ao);
    cudaGetSymbolAddress((void**)&qbuf, g_q);

    unsigned short *xh,*xl,*qlh,*qll,*ckh,*ckl,*aoh,*aol;
    unsigned short *WqaTh,*WqaTl,*WkvaTh,*WkvaTl,*WqbTh,*WqbTl,*WkvbTh,*WkvbTl,*WoTh,*WoTl;
    cudaGetSymbolAddress((void**)&xh,  g_xh);   cudaGetSymbolAddress((void**)&xl,  g_xl);
    cudaGetSymbolAddress((void**)&qlh, g_qlh);  cudaGetSymbolAddress((void**)&qll, g_qll);
    cudaGetSymbolAddress((void**)&ckh, g_ckh);  cudaGetSymbolAddress((void**)&ckl, g_ckl);
    cudaGetSymbolAddress((void**)&aoh, g_aoh);  cudaGetSymbolAddress((void**)&aol, g_aol);
    cudaGetSymbolAddress((void**)&WqaTh, g_WqaTh);   cudaGetSymbolAddress((void**)&WqaTl, g_WqaTl);
    cudaGetSymbolAddress((void**)&WkvaTh, g_WkvaTh); cudaGetSymbolAddress((void**)&WkvaTl, g_WkvaTl);
    cudaGetSymbolAddress((void**)&WqbTh, g_WqbTh);   cudaGetSymbolAddress((void**)&WqbTl, g_WqbTl);
    cudaGetSymbolAddress((void**)&WkvbTh, g_WkvbTh); cudaGetSymbolAddress((void**)&WkvbTl, g_WkvbTl);
    cudaGetSymbolAddress((void**)&WoTh, g_WoTh);     cudaGetSymbolAddress((void**)&WoTl, g_WoTl);

    cudaFuncSetAttribute(gemm_mma, cudaFuncAttributeMaxDynamicSharedMemorySize, GEMM_SMEM);
    cudaFuncSetAttribute(flash_kernel, cudaFuncAttributeMaxDynamicSharedMemorySize,
                         FLASH_SMEM_BYTES);
    dim3 blk(256);

    // prep: split x, transpose+split weights
    split2<<<(SEQ * DM + 255) / 256, blk>>>(x, xh, xl, SEQ * DM);
    transpose_split<<<dim3(QLORA / 32, DM / 32), blk>>>(Wqa, WqaTh, WqaTl, DM, QLORA);
    transpose_split<<<dim3(KVWP / 32, DM / 32), blk>>>(Wkva, WkvaTh, WkvaTl, DM, KVW);
    transpose_split<<<dim3(NQ / 32, QLORA / 32), blk>>>(Wqb, WqbTh, WqbTl, QLORA, NQ);
    transpose_split<<<dim3(NKV / 32, KVLORA / 32), blk>>>(Wkvb, WkvbTh, WkvbTl, KVLORA, NKV);
    transpose_split<<<dim3(DM / 32, DM / 32), blk>>>(Wo, WoTh, WoTl, DM, DM);

    // 1) qlat = x @ Wqa
    gemm_mma<<<dim3(QLORA / 128, SEQ / 128), blk, GEMM_SMEM>>>(
        xh, xl, DM, WqaTh, WqaTl, DM, qlat, QLORA, QLORA, DM);
    // 2) ckv = x @ Wkva   (N=576 valid, Npad=640)
    gemm_mma<<<dim3(KVWP / 128, SEQ / 128), blk, GEMM_SMEM>>>(
        xh, xl, DM, WkvaTh, WkvaTl, DM, ckv, KVW, KVW, DM);
    // 3/4) rmsnorms (fp32 in place)
    rmsnorm_kernel<<<SEQ, 256>>>(qlat, qln, QLORA, QLORA);
    rmsnorm_kernel<<<SEQ, 256>>>(ckv, kvln, KVLORA, KVW);
    // split normalized activations
    split2<<<(SEQ * QLORA + 255) / 256, blk>>>(qlat, qlh, qll, SEQ * QLORA);
    split2<<<(SEQ * KVW + 255) / 256, blk>>>(ckv, ckh, ckl, SEQ * KVW);
    // 5) q = qlat_n @ Wqb
    gemm_mma<<<dim3(NQ / 128, SEQ / 128), blk, GEMM_SMEM>>>(
        qlh, qll, QLORA, WqbTh, WqbTl, QLORA, qbuf, NQ, NQ, QLORA);
    // 6) kv = ckv_n @ Wkvb
    gemm_mma<<<dim3(NKV / 128, SEQ / 128), blk, GEMM_SMEM>>>(
        ckh, ckl, KVW, WkvbTh, WkvbTl, KVLORA, kv, NKV, NKV, KVLORA);
    // 7) rope + layout
    build_qk<<<SEQ, 256>>>(freqs);
    // 8) flash attention
    flash_kernel<<<dim3(SEQ / 64, NHEAD), blk, FLASH_SMEM_BYTES>>>(mask, ao);
    // 9) out = ao @ Wo
    split2<<<(SEQ * DM + 255) / 256, blk>>>(ao, aoh, aol, SEQ * DM);
    gemm_mma<<<dim3(DM / 128, SEQ / 128), blk, GEMM_SMEM>>>(
        aoh, aol, DM, WoTh, WoTl, DM, out, DM, DM, DM);
}

// round 9
// speedup vs baseline: 2.7792x; 2.1059x over previous
// R9: flash attention converted to HMMA (mma.sync bf16 hi/lo split, 3 terms),
// register softmax, ldmatrix.trans for V. GEMMs unchanged from R8 (3627.0us).
#include <cuda_runtime.h>
#include <cuda_bf16.h>
#include <math.h>
#include <stdint.h>

#define SEQ    2048
#define DM     2048
#define NHEAD  16
#define QLORA  1536
#define KVLORA 512
#define ROPED  64
#define NOPED  128
#define VD     128
#define QHDIM  192
#define KVW    576
#define KVROW  256
#define MASKW  2198
#define NEG_BIG (-1e30f)

#define NQ   (NHEAD * QHDIM)   // 3072
#define NKV  (NHEAD * KVROW)   // 4096
#define KVWP 640

// ---------------- fp32 scratch ----------------
__device__ float g_qlat[SEQ * QLORA];
__device__ float g_ckv [SEQ * KVW];
__device__ float g_q   [SEQ * NQ];
__device__ float g_kv  [SEQ * NKV];
__device__ float g_ao  [SEQ * DM];

// ---------------- bf16 hi/lo split buffers ----------------
__device__ unsigned short g_xh [SEQ * DM],    g_xl [SEQ * DM];
__device__ unsigned short g_qlh[SEQ * QLORA], g_qll[SEQ * QLORA];
__device__ unsigned short g_ckh[SEQ * KVW],   g_ckl[SEQ * KVW];
__device__ unsigned short g_aoh[SEQ * DM],    g_aol[SEQ * DM];
__device__ unsigned short g_WqaTh [QLORA * DM],  g_WqaTl [QLORA * DM];
__device__ unsigned short g_WkvaTh[KVWP  * DM],  g_WkvaTl[KVWP  * DM];
__device__ unsigned short g_WqbTh [NQ * QLORA],  g_WqbTl [NQ * QLORA];
__device__ unsigned short g_WkvbTh[NKV * KVLORA],g_WkvbTl[NKV * KVLORA];
__device__ unsigned short g_WoTh  [DM * DM],     g_WoTl  [DM * DM];
// attention operands, per-head [h][seq][dim] bf16 hi/lo
__device__ unsigned short g_Qbh[NHEAD * SEQ * QHDIM], g_Qbl[NHEAD * SEQ * QHDIM];
__device__ unsigned short g_Kbh[NHEAD * SEQ * QHDIM], g_Kbl[NHEAD * SEQ * QHDIM];
__device__ unsigned short g_Vbh[NHEAD * SEQ * VD],    g_Vbl[NHEAD * SEQ * VD];

// ======================= PTX helpers =======================
__device__ __forceinline__ uint32_t smem_u32(const void* p) {
    uint32_t a;
    asm("{ .reg .u64 t; cvta.to.shared.u64 t, %1; cvt.u32.u64 %0, t; }"
        : "=r"(a) : "l"(p));
    return a;
}
__device__ __forceinline__ void ldm_x4(uint32_t* r, uint32_t a) {
    asm volatile("ldmatrix.sync.aligned.m8n8.x4.shared.b16 {%0,%1,%2,%3}, [%4];"
        : "=r"(r[0]), "=r"(r[1]), "=r"(r[2]), "=r"(r[3]) : "r"(a));
}
__device__ __forceinline__ void ldm_x4_t(uint32_t* r, uint32_t a) {
    asm volatile("ldmatrix.sync.aligned.m8n8.x4.trans.shared.b16 {%0,%1,%2,%3}, [%4];"
        : "=r"(r[0]), "=r"(r[1]), "=r"(r[2]), "=r"(r[3]) : "r"(a));
}
__device__ __forceinline__ void mma16816(float* c, const uint32_t* a, const uint32_t* b) {
    asm volatile(
        "mma.sync.aligned.m16n8k16.row.col.f32.bf16.bf16.f32 "
        "{%0,%1,%2,%3}, {%4,%5,%6,%7}, {%8,%9}, {%0,%1,%2,%3};"
        : "+f"(c[0]), "+f"(c[1]), "+f"(c[2]), "+f"(c[3])
        : "r"(a[0]), "r"(a[1]), "r"(a[2]), "r"(a[3]), "r"(b[0]), "r"(b[1]));
}
__device__ __forceinline__ void bsplit(float v, unsigned short& h, unsigned short& l) {
    __nv_bfloat16 bh = __float2bfloat16(v);
    __nv_bfloat16 bl = __float2bfloat16(v - __bfloat162float(bh));
    h = __bfloat16_as_ushort(bh);
    l = __bfloat16_as_ushort(bl);
}
// pack two fp32 into bf16x2 hi-reg and residual lo-reg (x -> low half, y -> high)
__device__ __forceinline__ void hl_pack(float x, float y, uint32_t& hr, uint32_t& lr) {
    __nv_bfloat16 xh = __float2bfloat16(x);
    __nv_bfloat16 yh = __float2bfloat16(y);
    __nv_bfloat16 xl = __float2bfloat16(x - __bfloat162float(xh));
    __nv_bfloat16 yl = __float2bfloat16(y - __bfloat162float(yh));
    hr = (uint32_t)__bfloat16_as_ushort(xh) | ((uint32_t)__bfloat16_as_ushort(yh) << 16);
    lr = (uint32_t)__bfloat16_as_ushort(xl) | ((uint32_t)__bfloat16_as_ushort(yl) << 16);
}

// ======================= prep kernels =======================
__global__ void __launch_bounds__(256) split2(
    const float* __restrict__ src, unsigned short* __restrict__ h,
    unsigned short* __restrict__ l, int n)
{
    int i = blockIdx.x * 256 + threadIdx.x;
    if (i < n) bsplit(src[i], h[i], l[i]);
}

__global__ void __launch_bounds__(256) transpose_split(
    const float* __restrict__ W, unsigned short* __restrict__ Th,
    unsigned short* __restrict__ Tl, int K, int N)
{
    __shared__ float t[32][33];
    int n0 = blockIdx.x * 32, k0 = blockIdx.y * 32;
    int tx = threadIdx.x & 31, ty = threadIdx.x >> 5;
    #pragma unroll
    for (int i = 0; i < 4; i++) {
        int k = k0 + ty + i * 8, n = n0 + tx;
        t[ty + i * 8][tx] = (n < N) ? W[(size_t)k * N + n] : 0.f;
    }
    __syncthreads();
    #pragma unroll
    for (int i = 0; i < 4; i++) {
        int n = n0 + ty + i * 8, k = k0 + tx;
        bsplit(t[tx][ty + i * 8], Th[(size_t)n * K + k], Tl[(size_t)n * K + k]);
    }
}

// ======================= HMMA split GEMM (unchanged R8) =======================
#define T_STRIDE_US 40
#define TEN_US      (128 * 40)
#define STAGE_US    (4 * TEN_US)
#define GEMM_SMEM   (2 * STAGE_US * 2)

__global__ void __launch_bounds__(256) gemm_mma(
    const unsigned short* __restrict__ Ahp, const unsigned short* __restrict__ Alp, int lda,
    const unsigned short* __restrict__ Bhp, const unsigned short* __restrict__ Blp, int ldb,
    float* __restrict__ C, int ldc, int N, int K)
{
    extern __shared__ unsigned short smus[];
    const uint32_t sbase = smem_u32(smus);
    const int tid  = threadIdx.x;
    const int lane = tid & 31;
    const int wid  = tid >> 5;
    const int wm   = wid & 1;
    const int wn   = wid >> 1;
    const int row0 = blockIdx.y * 128;
    const int col0 = blockIdx.x * 128;

    const unsigned short* bases[4] = { Ahp, Alp, Bhp, Blp };
    const int ldv[4] = { lda, lda, ldb, ldb };
    const int rbv[4] = { row0, row0, col0, col0 };

    float acc[4][4][4];
    #pragma unroll
    for (int i = 0; i < 4; i++)
        #pragma unroll
        for (int j = 0; j < 4; j++)
            #pragma unroll
            for (int q = 0; q < 4; q++) acc[i][j][q] = 0.f;

    const int NC = K >> 5;
    const int a_r  = lane & 15;
    const int a_c  = (lane >> 4) * 16;
    const int b_q  = lane >> 3;
    const int b_r  = lane & 7;
    const uint32_t aoff = (uint32_t)((wm * 64 + a_r) * 80 + a_c);
    const uint32_t boff = (uint32_t)((wn * 32 + (b_q >> 1) * 8 + b_r) * 80 + (b_q & 1) * 16);

    {
        #pragma unroll
        for (int t = 0; t < 4; t++)
            #pragma unroll
            for (int i = 0; i < 2; i++) {
                int w = tid + i * 256;
                int r = w >> 2, c16 = w & 3;
                uint4 v = *(const uint4*)(bases[t] + (size_t)(rbv[t] + r) * ldv[t] + c16 * 8);
                *(uint4*)(smus + t * TEN_US + r * T_STRIDE_US + c16 * 8) = v;
            }
    }
    __syncthreads();

    for (int c = 0; c < NC; c++) {
        const int s = c & 1;
        if (c + 1 < NC) {
            const int k0 = (c + 1) << 5;
            #pragma unroll
            for (int t = 0; t < 4; t++)
                #pragma unroll
                for (int i = 0; i < 2; i++) {
                    int w = tid + i * 256;
                    int r = w >> 2, c16 = w & 3;
                    uint4 v = *(const uint4*)(bases[t] + (size_t)(rbv[t] + r) * ldv[t] + k0 + c16 * 8);
                    *(uint4*)(smus + (s ^ 1) * STAGE_US + t * TEN_US + r * T_STRIDE_US + c16 * 8) = v;
                }
        }
        const uint32_t st = sbase + (uint32_t)s * (STAGE_US * 2);
        #pragma unroll
        for (int ks = 0; ks < 2; ks++) {
            const uint32_t kb = (uint32_t)(ks * 32);
            uint32_t Ah[4][4], Al[4][4], Bh[4][2], Bl[4][2];
            #pragma unroll
            for (int mf = 0; mf < 4; mf++) {
                ldm_x4(Ah[mf], st + 0          + aoff + (uint32_t)(mf * 16 * 80) + kb);
                ldm_x4(Al[mf], st + TEN_US * 2 + aoff + (uint32_t)(mf * 16 * 80) + kb);
            }
            #pragma unroll
            for (int np = 0; np < 2; np++) {
                uint32_t rh[4], rl[4];
                ldm_x4(rh, st + TEN_US * 4 + boff + (uint32_t)(np * 16 * 80) + kb);
                ldm_x4(rl, st + TEN_US * 6 + boff + (uint32_t)(np * 16 * 80) + kb);
                Bh[np * 2][0] = rh[0]; Bh[np * 2][1] = rh[1];
                Bh[np * 2 + 1][0] = rh[2]; Bh[np * 2 + 1][1] = rh[3];
                Bl[np * 2][0] = rl[0]; Bl[np * 2][1] = rl[1];
                Bl[np * 2 + 1][0] = rl[2]; Bl[np * 2 + 1][1] = rl[3];
            }
            #pragma unroll
            for (int mf = 0; mf < 4; mf++)
                #pragma unroll
                for (int nf = 0; nf < 4; nf++) {
                    mma16816(acc[mf][nf], Ah[mf], Bh[nf]);
                    mma16816(acc[mf][nf], Ah[mf], Bl[nf]);
                    mma16816(acc[mf][nf], Al[mf], Bh[nf]);
                }
        }
        __syncthreads();
    }

    #pragma unroll
    for (int mf = 0; mf < 4; mf++) {
        int r0 = row0 + wm * 64 + mf * 16 + (lane >> 2);
        #pragma unroll
        for (int nf = 0; nf < 4; nf++) {
            int c0 = col0 + wn * 32 + nf * 8 + (lane & 3) * 2;
            if (c0 < N) {
                C[(size_t)r0 * ldc + c0] = acc[mf][nf][0];
                C[(size_t)(r0 + 8) * ldc + c0] = acc[mf][nf][2];
            }
            if (c0 + 1 < N) {
                C[(size_t)r0 * ldc + c0 + 1] = acc[mf][nf][1];
                C[(size_t)(r0 + 8) * ldc + c0 + 1] = acc[mf][nf][3];
            }
        }
    }
}

// ======================= rmsnorm =======================
__global__ void __launch_bounds__(256) rmsnorm_kernel(
    float* __restrict__ data, const float* __restrict__ w, int W, int ld)
{
    const int row = blockIdx.x;
    float* p = data + (size_t)row * ld;
    float ss = 0.f;
    for (int c = threadIdx.x; c < W; c += 256) { float v = p[c]; ss += v * v; }
    __shared__ float red[256];
    red[threadIdx.x] = ss;
    __syncthreads();
    #pragma unroll
    for (int s = 128; s > 0; s >>= 1) {
        if (threadIdx.x < s) red[threadIdx.x] += red[threadIdx.x + s];
        __syncthreads();
    }
    float scale = rsqrtf(red[0] / (float)W + 1e-6f);
    for (int c = threadIdx.x; c < W; c += 256) p[c] = w[c] * (p[c] * scale);
}

// ======================= rope + per-head bf16 hi/lo layout =================
__global__ void __launch_bounds__(256) build_qk(const float* __restrict__ freqs)
{
    const int s = blockIdx.x;
    const int tid = threadIdx.x;
    __shared__ float cs[32], sn[32];
    if (tid < 32) {
        cs[tid] = freqs[(s * 32 + tid) * 2 + 0];
        sn[tid] = freqs[(s * 32 + tid) * 2 + 1];
    }
    __syncthreads();

    const float* qrow = g_q + (size_t)s * NQ;
    for (int idx = tid; idx < NQ; idx += 256) {
        int hh = idx / QHDIM, d = idx % QHDIM;
        float val;
        if (d < ROPED) {
            int j = d >> 1;
            float a = qrow[hh * QHDIM + NOPED + 2 * j];
            float b = qrow[hh * QHDIM + NOPED + 2 * j + 1];
            val = (d & 1) ? (a * sn[j] + b * cs[j]) : (a * cs[j] - b * sn[j]);
        } else {
            val = qrow[hh * QHDIM + (d - ROPED)];
        }
        size_t off = ((size_t)hh * SEQ + s) * QHDIM + d;
        bsplit(val, g_Qbh[off], g_Qbl[off]);
    }

    const float* kperow = g_ckv + (size_t)s * KVW + KVLORA;
    const float* kvrow  = g_kv  + (size_t)s * NKV;
    for (int idx = tid; idx < NQ; idx += 256) {
        int hh = idx / QHDIM, d = idx % QHDIM;
        float val;
        if (d < ROPED) {
            int j = d >> 1;
            float a = kperow[2 * j], b = kperow[2 * j + 1];
            val = (d & 1) ? (a * sn[j] + b * cs[j]) : (a * cs[j] - b * sn[j]);
        } else {
            val = kvrow[hh * KVROW + (d - ROPED)];
        }
        size_t off = ((size_t)hh * SEQ + s) * QHDIM + d;
        bsplit(val, g_Kbh[off], g_Kbl[off]);
    }

    for (int idx = tid; idx < NHEAD * VD; idx += 256) {
        int hh = idx / VD, d = idx % VD;
        float v = kvrow[hh * KVROW + NOPED + d];
        size_t off = ((size_t)hh * SEQ + s) * VD + d;
        bsplit(v, g_Vbh[off], g_Vbl[off]);
    }
}

// ======================= HMMA flash attention =======================
// CTA: 128 Q rows x 1 head; 8 warps, warp owns 16 rows. kb step = 64 keys.
// smem (ushort offsets): Qh 0 (128x200), Ql 25600, Kh 51200 (64x200),
// Kl 64000, Vh 76800 (64x136), Vl 85504. Total 94208 us = 188416 B.
#define FL_SMEM_BYTES 188416

__global__ void __launch_bounds__(256) flash_mma(
    const int* __restrict__ mask, float* __restrict__ ao)
{
    extern __shared__ unsigned short fsm[];
    const uint32_t sb = smem_u32(fsm);
    const int tid  = threadIdx.x;
    const int lane = tid & 31;
    const int wq   = tid >> 5;
    const int qb   = blockIdx.x;
    const int h    = blockIdx.y;
    const int g    = lane >> 2;
    const int t    = lane & 3;
    const int bq   = lane >> 3;
    const int br   = lane & 7;
    const float scale = 0.088388347648318447f;   // 1/sqrt(128)

    unsigned short* Qh_s = fsm;
    unsigned short* Ql_s = fsm + 25600;
    unsigned short* Kh_s = fsm + 51200;
    unsigned short* Kl_s = fsm + 64000;
    unsigned short* Vh_s = fsm + 76800;
    unsigned short* Vl_s = fsm + 85504;

    // ldmatrix byte addresses (stride Q/K=400B, V=272B)
    const uint32_t aH = sb + (uint32_t)((wq * 16 + (lane & 15)) * 400 + (lane >> 4) * 16);
    const uint32_t aL = aH + 51200;
    const uint32_t kH = sb + 102400 + (uint32_t)(((bq >> 1) * 8 + br) * 400 + (bq & 1) * 16);
    const uint32_t kL = kH + 25600;
    const uint32_t vH = sb + 153600 + (uint32_t)(((bq & 1) * 8 + br) * 272 + (bq >> 1) * 16);
    const uint32_t vL = vH + 17408;

    // load Q tile (hi/lo)
    const size_t qgo = ((size_t)h * SEQ + (size_t)qb * 128) * QHDIM;
    for (int i = tid; i < 128 * 24; i += 256) {
        int r = i / 24, c = i % 24;
        *(uint4*)(Qh_s + r * 200 + c * 8) = *(const uint4*)(g_Qbh + qgo + (size_t)r * QHDIM + c * 8);
        *(uint4*)(Ql_s + r * 200 + c * 8) = *(const uint4*)(g_Qbl + qgo + (size_t)r * QHDIM + c * 8);
    }

    float o[16][4];
    #pragma unroll
    for (int i = 0; i < 16; i++)
        #pragma unroll
        for (int j = 0; j < 4; j++) o[i][j] = 0.f;
    float mr0 = NEG_BIG, mr1 = NEG_BIG, l0 = 0.f, l1 = 0.f;

    const int row0g = qb * 128 + wq * 16 + g;

    for (int kb = 0; kb < SEQ / 64; kb++) {
        __syncthreads();
        // load K tile (hi/lo)
        const size_t kgo = ((size_t)h * SEQ + (size_t)kb * 64) * QHDIM;
        for (int i = tid; i < 64 * 24; i += 256) {
            int r = i / 24, c = i % 24;
            *(uint4*)(Kh_s + r * 200 + c * 8) = *(const uint4*)(g_Kbh + kgo + (size_t)r * QHDIM + c * 8);
            *(uint4*)(Kl_s + r * 200 + c * 8) = *(const uint4*)(g_Kbl + kgo + (size_t)r * QHDIM + c * 8);
        }
        // load V tile (hi/lo)
        const size_t vgo = ((size_t)h * SEQ + (size_t)kb * 64) * VD;
        for (int i = tid; i < 64 * 16; i += 256) {
            int r = i / 16, c = i % 16;
            *(uint4*)(Vh_s + r * 136 + c * 8) = *(const uint4*)(g_Vbh + vgo + (size_t)r * VD + c * 8);
            *(uint4*)(Vl_s + r * 136 + c * 8) = *(const uint4*)(g_Vbl + vgo + (size_t)r * VD + c * 8);
        }
        __syncthreads();

        // ---- S = Q K^T (3-term split) ----
        float s[8][4];
        #pragma unroll
        for (int f = 0; f < 8; f++)
            #pragma unroll
            for (int e = 0; e < 4; e++) s[f][e] = 0.f;

        #pragma unroll
        for (int kk = 0; kk < 12; kk++) {
            uint32_t ah[4], al[4];
            ldm_x4(ah, aH + kk * 32);
            ldm_x4(al, aL + kk * 32);
            #pragma unroll
            for (int np = 0; np < 4; np++) {
                uint32_t bh[4], bl[4];
                ldm_x4(bh, kH + np * (16 * 400) + kk * 32);
                ldm_x4(bl, kL + np * (16 * 400) + kk * 32);
                mma16816(s[2 * np],     ah, bh);
                mma16816(s[2 * np],     ah, bl);
                mma16816(s[2 * np],     al, bh);
                mma16816(s[2 * np + 1], ah, bh + 2);
                mma16816(s[2 * np + 1], ah, bl + 2);
                mma16816(s[2 * np + 1], al, bh + 2);
            }
        }

        // ---- scale + mask ----
        #pragma unroll
        for (int f = 0; f < 8; f++)
            #pragma unroll
            for (int e = 0; e < 4; e++) s[f][e] *= scale;

        const int colbase = 150 + kb * 64;
        #pragma unroll
        for (int f = 0; f < 8; f++) {
            int col = colbase + f * 8 + 2 * t;
            int2 m0v = *(const int2*)(mask + (size_t)row0g * MASKW + col);
            int2 m1v = *(const int2*)(mask + (size_t)(row0g + 8) * MASKW + col);
            if (m0v.x == 1) s[f][0] = NEG_BIG;
            if (m0v.y == 1) s[f][1] = NEG_BIG;
            if (m1v.x == 1) s[f][2] = NEG_BIG;
            if (m1v.y == 1) s[f][3] = NEG_BIG;
        }

        // ---- online softmax (rows g and g+8; groups of 4 lanes) ----
        float m0 = NEG_BIG, m1 = NEG_BIG;
        #pragma unroll
        for (int f = 0; f < 8; f++) {
            m0 = fmaxf(m0, fmaxf(s[f][0], s[f][1]));
            m1 = fmaxf(m1, fmaxf(s[f][2], s[f][3]));
        }
        m0 = fmaxf(m0, __shfl_xor_sync(0xffffffffu, m0, 1));
        m0 = fmaxf(m0, __shfl_xor_sync(0xffffffffu, m0, 2));
        m1 = fmaxf(m1, __shfl_xor_sync(0xffffffffu, m1, 1));
        m1 = fmaxf(m1, __shfl_xor_sync(0xffffffffu, m1, 2));
        float nm0 = fmaxf(mr0, m0), nm1 = fmaxf(mr1, m1);
        float al0 = __expf(mr0 - nm0), al1 = __expf(mr1 - nm1);
        mr0 = nm0; mr1 = nm1;

        float sum0 = 0.f, sum1 = 0.f;
        #pragma unroll
        for (int f = 0; f < 8; f++) {
            s[f][0] = __expf(s[f][0] - nm0);
            s[f][1] = __expf(s[f][1] - nm0);
            s[f][2] = __expf(s[f][2] - nm1);
            s[f][3] = __expf(s[f][3] - nm1);
            sum0 += s[f][0] + s[f][1];
            sum1 += s[f][2] + s[f][3];
        }
        sum0 += __shfl_xor_sync(0xffffffffu, sum0, 1);
        sum0 += __shfl_xor_sync(0xffffffffu, sum0, 2);
        sum1 += __shfl_xor_sync(0xffffffffu, sum1, 1);
        sum1 += __shfl_xor_sync(0xffffffffu, sum1, 2);
        l0 = l0 * al0 + sum0;
        l1 = l1 * al1 + sum1;

        // rescale O
        #pragma unroll
        for (int nf = 0; nf < 16; nf++) {
            o[nf][0] *= al0; o[nf][1] *= al0;
            o[nf][2] *= al1; o[nf][3] *= al1;
        }

        // ---- P -> bf16 hi/lo A-frags (accum->A layout identity) ----
        uint32_t pah[4][4], pal[4][4];
        #pragma unroll
        for (int kk2 = 0; kk2 < 4; kk2++) {
            hl_pack(s[2 * kk2][0],     s[2 * kk2][1],     pah[kk2][0], pal[kk2][0]);
            hl_pack(s[2 * kk2][2],     s[2 * kk2][3],     pah[kk2][1], pal[kk2][1]);
            hl_pack(s[2 * kk2 + 1][0], s[2 * kk2 + 1][1], pah[kk2][2], pal[kk2][2]);
            hl_pack(s[2 * kk2 + 1][2], s[2 * kk2 + 1][3], pah[kk2][3], pal[kk2][3]);
        }

        // ---- O += P V (3-term split, V via ldmatrix.trans) ----
        #pragma unroll
        for (int kk2 = 0; kk2 < 4; kk2++) {
            #pragma unroll
            for (int jj = 0; jj < 8; jj++) {
                uint32_t vh4[4], vl4[4];
                ldm_x4_t(vh4, vH + kk2 * (16 * 272) + jj * 32);
                ldm_x4_t(vl4, vL + kk2 * (16 * 272) + jj * 32);
                mma16816(o[2 * jj],     pah[kk2], vh4);
                mma16816(o[2 * jj],     pah[kk2], vl4);
                mma16816(o[2 * jj],     pal[kk2], vh4);
                mma16816(o[2 * jj + 1], pah[kk2], vh4 + 2);
                mma16816(o[2 * jj + 1], pah[kk2], vl4 + 2);
                mma16816(o[2 * jj + 1], pal[kk2], vh4 + 2);
            }
        }
    }

    const float inv0 = 1.f / l0, inv1 = 1.f / l1;
    #pragma unroll
    for (int nf = 0; nf < 16; nf++) {
        int col = h * VD + nf * 8 + 2 * t;
        *(float2*)(ao + (size_t)row0g * DM + col) =
            make_float2(o[nf][0] * inv0, o[nf][1] * inv0);
        *(float2*)(ao + (size_t)(row0g + 8) * DM + col) =
            make_float2(o[nf][2] * inv1, o[nf][3] * inv1);
    }
}

// ---------------------------------------------------------------------------
extern "C" void kernel_launch(void* const* d_in, const int* in_sizes, int n_in,
                              void* d_out, int out_size)
{
    const float* x     = (const float*)d_in[0];
    const int*   mask  = (const int*)  d_in[1];
    const float* freqs = (const float*)d_in[2];
    const float* Wqa   = (const float*)d_in[3];
    const float* qln   = (const float*)d_in[4];
    const float* Wqb   = (const float*)d_in[5];
    const float* Wkva  = (const float*)d_in[6];
    const float* kvln  = (const float*)d_in[7];
    const float* Wkvb  = (const float*)d_in[8];
    const float* Wo    = (const float*)d_in[9];
    float* out = (float*)d_out;

    float *qlat, *ckv, *kv, *ao, *qbuf;
    cudaGetSymbolAddress((void**)&qlat, g_qlat);
    cudaGetSymbolAddress((void**)&ckv,  g_ckv);
    cudaGetSymbolAddress((void**)&kv,   g_kv);
    cudaGetSymbolAddress((void**)&ao,   g_ao);
    cudaGetSymbolAddress((void**)&qbuf, g_q);

    unsigned short *xh,*xl,*qlh,*qll,*ckh,*ckl,*aoh,*aol;
    unsigned short *WqaTh,*WqaTl,*WkvaTh,*WkvaTl,*WqbTh,*WqbTl,*WkvbTh,*WkvbTl,*WoTh,*WoTl;
    cudaGetSymbolAddress((void**)&xh,  g_xh);   cudaGetSymbolAddress((void**)&xl,  g_xl);
    cudaGetSymbolAddress((void**)&qlh, g_qlh);  cudaGetSymbolAddress((void**)&qll, g_qll);
    cudaGetSymbolAddress((void**)&ckh, g_ckh);  cudaGetSymbolAddress((void**)&ckl, g_ckl);
    cudaGetSymbolAddress((void**)&aoh, g_aoh);  cudaGetSymbolAddress((void**)&aol, g_aol);
    cudaGetSymbolAddress((void**)&WqaTh, g_WqaTh);   cudaGetSymbolAddress((void**)&WqaTl, g_WqaTl);
    cudaGetSymbolAddress((void**)&WkvaTh, g_WkvaTh); cudaGetSymbolAddress((void**)&WkvaTl, g_WkvaTl);
    cudaGetSymbolAddress((void**)&WqbTh, g_WqbTh);   cudaGetSymbolAddress((void**)&WqbTl, g_WqbTl);
    cudaGetSymbolAddress((void**)&WkvbTh, g_WkvbTh); cudaGetSymbolAddress((void**)&WkvbTl, g_WkvbTl);
    cudaGetSymbolAddress((void**)&WoTh, g_WoTh);     cudaGetSymbolAddress((void**)&WoTl, g_WoTl);

    cudaFuncSetAttribute(gemm_mma, cudaFuncAttributeMaxDynamicSharedMemorySize, GEMM_SMEM);
    cudaFuncSetAttribute(flash_mma, cudaFuncAttributeMaxDynamicSharedMemorySize, FL_SMEM_BYTES);
    dim3 blk(256);

    // prep
    split2<<<(SEQ * DM + 255) / 256, blk>>>(x, xh, xl, SEQ * DM);
    transpose_split<<<dim3(QLORA / 32, DM / 32), blk>>>(Wqa, WqaTh, WqaTl, DM, QLORA);
    transpose_split<<<dim3(KVWP / 32, DM / 32), blk>>>(Wkva, WkvaTh, WkvaTl, DM, KVW);
    transpose_split<<<dim3(NQ / 32, QLORA / 32), blk>>>(Wqb, WqbTh, WqbTl, QLORA, NQ);
    transpose_split<<<dim3(NKV / 32, KVLORA / 32), blk>>>(Wkvb, WkvbTh, WkvbTl, KVLORA, NKV);
    transpose_split<<<dim3(DM / 32, DM / 32), blk>>>(Wo, WoTh, WoTl, DM, DM);

    // projections
    gemm_mma<<<dim3(QLORA / 128, SEQ / 128), blk, GEMM_SMEM>>>(
        xh, xl, DM, WqaTh, WqaTl, DM, qlat, QLORA, QLORA, DM);
    gemm_mma<<<dim3(KVWP / 128, SEQ / 128), blk, GEMM_SMEM>>>(
        xh, xl, DM, WkvaTh, WkvaTl, DM, ckv, KVW, KVW, DM);
    rmsnorm_kernel<<<SEQ, 256>>>(qlat, qln, QLORA, QLORA);
    rmsnorm_kernel<<<SEQ, 256>>>(ckv, kvln, KVLORA, KVW);
    split2<<<(SEQ * QLORA + 255) / 256, blk>>>(qlat, qlh, qll, SEQ * QLORA);
    split2<<<(SEQ * KVW + 255) / 256, blk>>>(ckv, ckh, ckl, SEQ * KVW);
    gemm_mma<<<dim3(NQ / 128, SEQ / 128), blk, GEMM_SMEM>>>(
        qlh, qll, QLORA, WqbTh, WqbTl, QLORA, qbuf, NQ, NQ, QLORA);
    gemm_mma<<<dim3(NKV / 128, SEQ / 128), blk, GEMM_SMEM>>>(
        ckh, ckl, KVW, WkvbTh, WkvbTl, KVLORA, kv, NKV, NKV, KVLORA);

    // rope + bf16 hi/lo per-head layout
    build_qk<<<SEQ, 256>>>(freqs);

    // HMMA flash attention
    flash_mma<<<dim3(SEQ / 128, NHEAD), blk, FL_SMEM_BYTES>>>(mask, ao);

    // output projection
    split2<<<(SEQ * DM + 255) / 256, blk>>>(ao, aoh, aol, SEQ * DM);
    gemm_mma<<<dim3(DM / 128, SEQ / 128), blk, GEMM_SMEM>>>(
        aoh, aol, DM, WoTh, WoTl, DM, out, DM, DM, DM);
}

// round 10
// speedup vs baseline: 3.0699x; 1.1046x over previous
// R10: gemm_mma converted to cp.async 2-stage pipeline (removes LDG->reg->STS
// round-trip + latency exposure); launches reordered so ncu -s 5 profiles gemm1.
// Flash (HMMA, R9) unchanged. Best: R9 = 1722.3us.
#include <cuda_runtime.h>
#include <cuda_bf16.h>
#include <math.h>
#include <stdint.h>

#define SEQ    2048
#define DM     2048
#define NHEAD  16
#define QLORA  1536
#define KVLORA 512
#define ROPED  64
#define NOPED  128
#define VD     128
#define QHDIM  192
#define KVW    576
#define KVROW  256
#define MASKW  2198
#define NEG_BIG (-1e30f)

#define NQ   (NHEAD * QHDIM)   // 3072
#define NKV  (NHEAD * KVROW)   // 4096
#define KVWP 640

// ---------------- fp32 scratch ----------------
__device__ float g_qlat[SEQ * QLORA];
__device__ float g_ckv [SEQ * KVW];
__device__ float g_q   [SEQ * NQ];
__device__ float g_kv  [SEQ * NKV];
__device__ float g_ao  [SEQ * DM];

// ---------------- bf16 hi/lo split buffers ----------------
__device__ unsigned short g_xh [SEQ * DM],    g_xl [SEQ * DM];
__device__ unsigned short g_qlh[SEQ * QLORA], g_qll[SEQ * QLORA];
__device__ unsigned short g_ckh[SEQ * KVW],   g_ckl[SEQ * KVW];
__device__ unsigned short g_aoh[SEQ * DM],    g_aol[SEQ * DM];
__device__ unsigned short g_WqaTh [QLORA * DM],  g_WqaTl [QLORA * DM];
__device__ unsigned short g_WkvaTh[KVWP  * DM],  g_WkvaTl[KVWP  * DM];
__device__ unsigned short g_WqbTh [NQ * QLORA],  g_WqbTl [NQ * QLORA];
__device__ unsigned short g_WkvbTh[NKV * KVLORA],g_WkvbTl[NKV * KVLORA];
__device__ unsigned short g_WoTh  [DM * DM],     g_WoTl  [DM * DM];
__device__ unsigned short g_Qbh[NHEAD * SEQ * QHDIM], g_Qbl[NHEAD * SEQ * QHDIM];
__device__ unsigned short g_Kbh[NHEAD * SEQ * QHDIM], g_Kbl[NHEAD * SEQ * QHDIM];
__device__ unsigned short g_Vbh[NHEAD * SEQ * VD],    g_Vbl[NHEAD * SEQ * VD];

// ======================= PTX helpers =======================
__device__ __forceinline__ uint32_t smem_u32(const void* p) {
    uint32_t a;
    asm("{ .reg .u64 t; cvta.to.shared.u64 t, %1; cvt.u32.u64 %0, t; }"
        : "=r"(a) : "l"(p));
    return a;
}
__device__ __forceinline__ void ldm_x4(uint32_t* r, uint32_t a) {
    asm volatile("ldmatrix.sync.aligned.m8n8.x4.shared.b16 {%0,%1,%2,%3}, [%4];"
        : "=r"(r[0]), "=r"(r[1]), "=r"(r[2]), "=r"(r[3]) : "r"(a));
}
__device__ __forceinline__ void ldm_x4_t(uint32_t* r, uint32_t a) {
    asm volatile("ldmatrix.sync.aligned.m8n8.x4.trans.shared.b16 {%0,%1,%2,%3}, [%4];"
        : "=r"(r[0]), "=r"(r[1]), "=r"(r[2]), "=r"(r[3]) : "r"(a));
}
__device__ __forceinline__ void mma16816(float* c, const uint32_t* a, const uint32_t* b) {
    asm volatile(
        "mma.sync.aligned.m16n8k16.row.col.f32.bf16.bf16.f32 "
        "{%0,%1,%2,%3}, {%4,%5,%6,%7}, {%8,%9}, {%0,%1,%2,%3};"
        : "+f"(c[0]), "+f"(c[1]), "+f"(c[2]), "+f"(c[3])
        : "r"(a[0]), "r"(a[1]), "r"(a[2]), "r"(a[3]), "r"(b[0]), "r"(b[1]));
}
__device__ __forceinline__ void cp16(uint32_t dst, const void* src) {
    asm volatile("cp.async.cg.shared.global [%0], [%1], 16;" :: "r"(dst), "l"(src));
}
#define CP_COMMIT() asm volatile("cp.async.commit_group;" ::: "memory")
#define CP_WAIT0()  asm volatile("cp.async.wait_group 0;" ::: "memory")
#define CP_WAIT1()  asm volatile("cp.async.wait_group 1;" ::: "memory")

__device__ __forceinline__ void bsplit(float v, unsigned short& h, unsigned short& l) {
    __nv_bfloat16 bh = __float2bfloat16(v);
    __nv_bfloat16 bl = __float2bfloat16(v - __bfloat162float(bh));
    h = __bfloat16_as_ushort(bh);
    l = __bfloat16_as_ushort(bl);
}
__device__ __forceinline__ void hl_pack(float x, float y, uint32_t& hr, uint32_t& lr) {
    __nv_bfloat16 xh = __float2bfloat16(x);
    __nv_bfloat16 yh = __float2bfloat16(y);
    __nv_bfloat16 xl = __float2bfloat16(x - __bfloat162float(xh));
    __nv_bfloat16 yl = __float2bfloat16(y - __bfloat162float(yh));
    hr = (uint32_t)__bfloat16_as_ushort(xh) | ((uint32_t)__bfloat16_as_ushort(yh) << 16);
    lr = (uint32_t)__bfloat16_as_ushort(xl) | ((uint32_t)__bfloat16_as_ushort(yl) << 16);
}

// ======================= prep kernels =======================
__global__ void __launch_bounds__(256) split2(
    const float* __restrict__ src, unsigned short* __restrict__ h,
    unsigned short* __restrict__ l, int n)
{
    int i = blockIdx.x * 256 + threadIdx.x;
    if (i < n) bsplit(src[i], h[i], l[i]);
}

__global__ void __launch_bounds__(256) transpose_split(
    const float* __restrict__ W, unsigned short* __restrict__ Th,
    unsigned short* __restrict__ Tl, int K, int N)
{
    __shared__ float t[32][33];
    int n0 = blockIdx.x * 32, k0 = blockIdx.y * 32;
    int tx = threadIdx.x & 31, ty = threadIdx.x >> 5;
    #pragma unroll
    for (int i = 0; i < 4; i++) {
        int k = k0 + ty + i * 8, n = n0 + tx;
        t[ty + i * 8][tx] = (n < N) ? W[(size_t)k * N + n] : 0.f;
    }
    __syncthreads();
    #pragma unroll
    for (int i = 0; i < 4; i++) {
        int n = n0 + ty + i * 8, k = k0 + tx;
        bsplit(t[tx][ty + i * 8], Th[(size_t)n * K + k], Tl[(size_t)n * K + k]);
    }
}

// ======================= HMMA split GEMM, cp.async 2-stage ================
#define T_STRIDE_US 40
#define TEN_US      (128 * 40)
#define STAGE_US    (4 * TEN_US)
#define GEMM_SMEM   (2 * STAGE_US * 2)

__global__ void __launch_bounds__(256) gemm_mma(
    const unsigned short* __restrict__ Ahp, const unsigned short* __restrict__ Alp, int lda,
    const unsigned short* __restrict__ Bhp, const unsigned short* __restrict__ Blp, int ldb,
    float* __restrict__ C, int ldc, int N, int K)
{
    extern __shared__ unsigned short smus[];
    const uint32_t sbase = smem_u32(smus);
    const int tid  = threadIdx.x;
    const int lane = tid & 31;
    const int wid  = tid >> 5;
    const int wm   = wid & 1;
    const int wn   = wid >> 1;
    const int row0 = blockIdx.y * 128;
    const int col0 = blockIdx.x * 128;

    const unsigned short* bases[4] = { Ahp, Alp, Bhp, Blp };
    const int ldv[4] = { lda, lda, ldb, ldb };
    const int rbv[4] = { row0, row0, col0, col0 };

    // per-thread copy mapping: 2 rows-per-tensor, 8 x 16B total
    const int cp_r  = tid >> 2;       // 0..63 base row (x2 via +64? no: w= tid + i*256)
    const int cp_c  = tid & 3;        // 16B chunk

    float acc[4][4][4];
    #pragma unroll
    for (int i = 0; i < 4; i++)
        #pragma unroll
        for (int j = 0; j < 4; j++)
            #pragma unroll
            for (int q = 0; q < 4; q++) acc[i][j][q] = 0.f;

    const int NC = K >> 5;
    const int a_r  = lane & 15;
    const int a_c  = (lane >> 4) * 16;
    const int b_q  = lane >> 3;
    const int b_r  = lane & 7;
    const uint32_t aoff = (uint32_t)((wm * 64 + a_r) * 80 + a_c);
    const uint32_t boff = (uint32_t)((wn * 32 + (b_q >> 1) * 8 + b_r) * 80 + (b_q & 1) * 16);

    // issue copies for chunk -> stage
    auto issue_chunk = [&](int k0, int s) {
        const uint32_t sb = sbase + (uint32_t)s * (STAGE_US * 2);
        #pragma unroll
        for (int t = 0; t < 4; t++)
            #pragma unroll
            for (int i = 0; i < 2; i++) {
                int r = cp_r + i * 64;
                cp16(sb + (uint32_t)(t * TEN_US + r * T_STRIDE_US + cp_c * 8) * 2,
                     bases[t] + (size_t)(rbv[t] + r) * ldv[t] + k0 + cp_c * 8);
            }
        CP_COMMIT();
    };

    issue_chunk(0, 0);

    for (int c = 0; c < NC; c++) {
        const int s = c & 1;
        if (c + 1 < NC) { issue_chunk((c + 1) << 5, s ^ 1); CP_WAIT1(); }
        else            { CP_WAIT0(); }
        __syncthreads();

        const uint32_t st = sbase + (uint32_t)s * (STAGE_US * 2);
        #pragma unroll
        for (int ks = 0; ks < 2; ks++) {
            const uint32_t kb = (uint32_t)(ks * 32);
            uint32_t Ah[4][4], Al[4][4], Bh[4][2], Bl[4][2];
            #pragma unroll
            for (int mf = 0; mf < 4; mf++) {
                ldm_x4(Ah[mf], st + 0          + aoff + (uint32_t)(mf * 16 * 80) + kb);
                ldm_x4(Al[mf], st + TEN_US * 2 + aoff + (uint32_t)(mf * 16 * 80) + kb);
            }
            #pragma unroll
            for (int np = 0; np < 2; np++) {
                uint32_t rh[4], rl[4];
                ldm_x4(rh, st + TEN_US * 4 + boff + (uint32_t)(np * 16 * 80) + kb);
                ldm_x4(rl, st + TEN_US * 6 + boff + (uint32_t)(np * 16 * 80) + kb);
                Bh[np * 2][0] = rh[0]; Bh[np * 2][1] = rh[1];
                Bh[np * 2 + 1][0] = rh[2]; Bh[np * 2 + 1][1] = rh[3];
                Bl[np * 2][0] = rl[0]; Bl[np * 2][1] = rl[1];
                Bl[np * 2 + 1][0] = rl[2]; Bl[np * 2 + 1][1] = rl[3];
            }
            #pragma unroll
            for (int mf = 0; mf < 4; mf++)
                #pragma unroll
                for (int nf = 0; nf < 4; nf++) {
                    mma16816(acc[mf][nf], Ah[mf], Bh[nf]);
                    mma16816(acc[mf][nf], Ah[mf], Bl[nf]);
                    mma16816(acc[mf][nf], Al[mf], Bh[nf]);
                }
        }
        __syncthreads();
    }

    #pragma unroll
    for (int mf = 0; mf < 4; mf++) {
        int r0 = row0 + wm * 64 + mf * 16 + (lane >> 2);
        #pragma unroll
        for (int nf = 0; nf < 4; nf++) {
            int c0 = col0 + wn * 32 + nf * 8 + (lane & 3) * 2;
            if (c0 < N) {
                C[(size_t)r0 * ldc + c0] = acc[mf][nf][0];
                C[(size_t)(r0 + 8) * ldc + c0] = acc[mf][nf][2];
            }
            if (c0 + 1 < N) {
                C[(size_t)r0 * ldc + c0 + 1] = acc[mf][nf][1];
                C[(size_t)(r0 + 8) * ldc + c0 + 1] = acc[mf][nf][3];
            }
        }
    }
}

// ======================= rmsnorm =======================
__global__ void __launch_bounds__(256) rmsnorm_kernel(
    float* __restrict__ data, const float* __restrict__ w, int W, int ld)
{
    const int row = blockIdx.x;
    float* p = data + (size_t)row * ld;
    float ss = 0.f;
    for (int c = threadIdx.x; c < W; c += 256) { float v = p[c]; ss += v * v; }
    __shared__ float red[256];
    red[threadIdx.x] = ss;
    __syncthreads();
    #pragma unroll
    for (int s = 128; s > 0; s >>= 1) {
        if (threadIdx.x < s) red[threadIdx.x] += red[threadIdx.x + s];
        __syncthreads();
    }
    float scale = rsqrtf(red[0] / (float)W + 1e-6f);
    for (int c = threadIdx.x; c < W; c += 256) p[c] = w[c] * (p[c] * scale);
}

// ======================= rope + per-head bf16 hi/lo layout =================
__global__ void __launch_bounds__(256) build_qk(const float* __restrict__ freqs)
{
    const int s = blockIdx.x;
    const int tid = threadIdx.x;
    __shared__ float cs[32], sn[32];
    if (tid < 32) {
        cs[tid] = freqs[(s * 32 + tid) * 2 + 0];
        sn[tid] = freqs[(s * 32 + tid) * 2 + 1];
    }
    __syncthreads();

    const float* qrow = g_q + (size_t)s * NQ;
    for (int idx = tid; idx < NQ; idx += 256) {
        int hh = idx / QHDIM, d = idx % QHDIM;
        float val;
        if (d < ROPED) {
            int j = d >> 1;
            float a = qrow[hh * QHDIM + NOPED + 2 * j];
            float b = qrow[hh * QHDIM + NOPED + 2 * j + 1];
            val = (d & 1) ? (a * sn[j] + b * cs[j]) : (a * cs[j] - b * sn[j]);
        } else {
            val = qrow[hh * QHDIM + (d - ROPED)];
        }
        size_t off = ((size_t)hh * SEQ + s) * QHDIM + d;
        bsplit(val, g_Qbh[off], g_Qbl[off]);
    }

    const float* kperow = g_ckv + (size_t)s * KVW + KVLORA;
    const float* kvrow  = g_kv  + (size_t)s * NKV;
    for (int idx = tid; idx < NQ; idx += 256) {
        int hh = idx / QHDIM, d = idx % QHDIM;
        float val;
        if (d < ROPED) {
            int j = d >> 1;
            float a = kperow[2 * j], b = kperow[2 * j + 1];
            val = (d & 1) ? (a * sn[j] + b * cs[j]) : (a * cs[j] - b * sn[j]);
        } else {
            val = kvrow[hh * KVROW + (d - ROPED)];
        }
        size_t off = ((size_t)hh * SEQ + s) * QHDIM + d;
        bsplit(val, g_Kbh[off], g_Kbl[off]);
    }

    for (int idx = tid; idx < NHEAD * VD; idx += 256) {
        int hh = idx / VD, d = idx % VD;
        float v = kvrow[hh * KVROW + NOPED + d];
        size_t off = ((size_t)hh * SEQ + s) * VD + d;
        bsplit(v, g_Vbh[off], g_Vbl[off]);
    }
}

// ======================= HMMA flash attention (unchanged R9) ==============
#define FL_SMEM_BYTES 188416

__global__ void __launch_bounds__(256) flash_mma(
    const int* __restrict__ mask, float* __restrict__ ao)
{
    extern __shared__ unsigned short fsm[];
    const uint32_t sb = smem_u32(fsm);
    const int tid  = threadIdx.x;
    const int lane = tid & 31;
    const int wq   = tid >> 5;
    const int qb   = blockIdx.x;
    const int h    = blockIdx.y;
    const int g    = lane >> 2;
    const int t    = lane & 3;
    const int bq   = lane >> 3;
    const int br   = lane & 7;
    const float scale = 0.088388347648318447f;

    unsigned short* Qh_s = fsm;
    unsigned short* Ql_s = fsm + 25600;
    unsigned short* Kh_s = fsm + 51200;
    unsigned short* Kl_s = fsm + 64000;
    unsigned short* Vh_s = fsm + 76800;
    unsigned short* Vl_s = fsm + 85504;

    const uint32_t aH = sb + (uint32_t)((wq * 16 + (lane & 15)) * 400 + (lane >> 4) * 16);
    const uint32_t aL = aH + 51200;
    const uint32_t kH = sb + 102400 + (uint32_t)(((bq >> 1) * 8 + br) * 400 + (bq & 1) * 16);
    const uint32_t kL = kH + 25600;
    const uint32_t vH = sb + 153600 + (uint32_t)(((bq & 1) * 8 + br) * 272 + (bq >> 1) * 16);
    const uint32_t vL = vH + 17408;

    const size_t qgo = ((size_t)h * SEQ + (size_t)qb * 128) * QHDIM;
    for (int i = tid; i < 128 * 24; i += 256) {
        int r = i / 24, c = i % 24;
        *(uint4*)(Qh_s + r * 200 + c * 8) = *(const uint4*)(g_Qbh + qgo + (size_t)r * QHDIM + c * 8);
        *(uint4*)(Ql_s + r * 200 + c * 8) = *(const uint4*)(g_Qbl + qgo + (size_t)r * QHDIM + c * 8);
    }

    float o[16][4];
    #pragma unroll
    for (int i = 0; i < 16; i++)
        #pragma unroll
        for (int j = 0; j < 4; j++) o[i][j] = 0.f;
    float mr0 = NEG_BIG, mr1 = NEG_BIG, l0 = 0.f, l1 = 0.f;

    const int row0g = qb * 128 + wq * 16 + g;

    for (int kb = 0; kb < SEQ / 64; kb++) {
        __syncthreads();
        const size_t kgo = ((size_t)h * SEQ + (size_t)kb * 64) * QHDIM;
        for (int i = tid; i < 64 * 24; i += 256) {
            int r = i / 24, c = i % 24;
            *(uint4*)(Kh_s + r * 200 + c * 8) = *(const uint4*)(g_Kbh + kgo + (size_t)r * QHDIM + c * 8);
            *(uint4*)(Kl_s + r * 200 + c * 8) = *(const uint4*)(g_Kbl + kgo + (size_t)r * QHDIM + c * 8);
        }
        const size_t vgo = ((size_t)h * SEQ + (size_t)kb * 64) * VD;
        for (int i = tid; i < 64 * 16; i += 256) {
            int r = i / 16, c = i % 16;
            *(uint4*)(Vh_s + r * 136 + c * 8) = *(const uint4*)(g_Vbh + vgo + (size_t)r * VD + c * 8);
            *(uint4*)(Vl_s + r * 136 + c * 8) = *(const uint4*)(g_Vbl + vgo + (size_t)r * VD + c * 8);
        }
        __syncthreads();

        float s[8][4];
        #pragma unroll
        for (int f = 0; f < 8; f++)
            #pragma unroll
            for (int e = 0; e < 4; e++) s[f][e] = 0.f;

        #pragma unroll
        for (int kk = 0; kk < 12; kk++) {
            uint32_t ah[4], al[4];
            ldm_x4(ah, aH + kk * 32);
            ldm_x4(al, aL + kk * 32);
            #pragma unroll
            for (int np = 0; np < 4; np++) {
                uint32_t bh[4], bl[4];
                ldm_x4(bh, kH + np * (16 * 400) + kk * 32);
                ldm_x4(bl, kL + np * (16 * 400) + kk * 32);
                mma16816(s[2 * np],     ah, bh);
                mma16816(s[2 * np],     ah, bl);
                mma16816(s[2 * np],     al, bh);
                mma16816(s[2 * np + 1], ah, bh + 2);
                mma16816(s[2 * np + 1], ah, bl + 2);
                mma16816(s[2 * np + 1], al, bh + 2);
            }
        }

        #pragma unroll
        for (int f = 0; f < 8; f++)
            #pragma unroll
            for (int e = 0; e < 4; e++) s[f][e] *= scale;

        const int colbase = 150 + kb * 64;
        #pragma unroll
        for (int f = 0; f < 8; f++) {
            int col = colbase + f * 8 + 2 * t;
            int2 m0v = *(const int2*)(mask + (size_t)row0g * MASKW + col);
            int2 m1v = *(const int2*)(mask + (size_t)(row0g + 8) * MASKW + col);
            if (m0v.x == 1) s[f][0] = NEG_BIG;
            if (m0v.y == 1) s[f][1] = NEG_BIG;
            if (m1v.x == 1) s[f][2] = NEG_BIG;
            if (m1v.y == 1) s[f][3] = NEG_BIG;
        }

        float m0 = NEG_BIG, m1 = NEG_BIG;
        #pragma unroll
        for (int f = 0; f < 8; f++) {
            m0 = fmaxf(m0, fmaxf(s[f][0], s[f][1]));
            m1 = fmaxf(m1, fmaxf(s[f][2], s[f][3]));
        }
        m0 = fmaxf(m0, __shfl_xor_sync(0xffffffffu, m0, 1));
        m0 = fmaxf(m0, __shfl_xor_sync(0xffffffffu, m0, 2));
        m1 = fmaxf(m1, __shfl_xor_sync(0xffffffffu, m1, 1));
        m1 = fmaxf(m1, __shfl_xor_sync(0xffffffffu, m1, 2));
        float nm0 = fmaxf(mr0, m0), nm1 = fmaxf(mr1, m1);
        float al0 = __expf(mr0 - nm0), al1 = __expf(mr1 - nm1);
        mr0 = nm0; mr1 = nm1;

        float sum0 = 0.f, sum1 = 0.f;
        #pragma unroll
        for (int f = 0; f < 8; f++) {
            s[f][0] = __expf(s[f][0] - nm0);
            s[f][1] = __expf(s[f][1] - nm0);
            s[f][2] = __expf(s[f][2] - nm1);
            s[f][3] = __expf(s[f][3] - nm1);
            sum0 += s[f][0] + s[f][1];
            sum1 += s[f][2] + s[f][3];
        }
        sum0 += __shfl_xor_sync(0xffffffffu, sum0, 1);
        sum0 += __shfl_xor_sync(0xffffffffu, sum0, 2);
        sum1 += __shfl_xor_sync(0xffffffffu, sum1, 1);
        sum1 += __shfl_xor_sync(0xffffffffu, sum1, 2);
        l0 = l0 * al0 + sum0;
        l1 = l1 * al1 + sum1;

        #pragma unroll
        for (int nf = 0; nf < 16; nf++) {
            o[nf][0] *= al0; o[nf][1] *= al0;
            o[nf][2] *= al1; o[nf][3] *= al1;
        }

        uint32_t pah[4][4], pal[4][4];
        #pragma unroll
        for (int kk2 = 0; kk2 < 4; kk2++) {
            hl_pack(s[2 * kk2][0],     s[2 * kk2][1],     pah[kk2][0], pal[kk2][0]);
            hl_pack(s[2 * kk2][2],     s[2 * kk2][3],     pah[kk2][1], pal[kk2][1]);
            hl_pack(s[2 * kk2 + 1][0], s[2 * kk2 + 1][1], pah[kk2][2], pal[kk2][2]);
            hl_pack(s[2 * kk2 + 1][2], s[2 * kk2 + 1][3], pah[kk2][3], pal[kk2][3]);
        }

        #pragma unroll
        for (int kk2 = 0; kk2 < 4; kk2++) {
            #pragma unroll
            for (int jj = 0; jj < 8; jj++) {
                uint32_t vh4[4], vl4[4];
                ldm_x4_t(vh4, vH + kk2 * (16 * 272) + jj * 32);
                ldm_x4_t(vl4, vL + kk2 * (16 * 272) + jj * 32);
                mma16816(o[2 * jj],     pah[kk2], vh4);
                mma16816(o[2 * jj],     pah[kk2], vl4);
                mma16816(o[2 * jj],     pal[kk2], vh4);
                mma16816(o[2 * jj + 1], pah[kk2], vh4 + 2);
                mma16816(o[2 * jj + 1], pah[kk2], vl4 + 2);
                mma16816(o[2 * jj + 1], pal[kk2], vh4 + 2);
            }
        }
    }

    const float inv0 = 1.f / l0, inv1 = 1.f / l1;
    #pragma unroll
    for (int nf = 0; nf < 16; nf++) {
        int col = h * VD + nf * 8 + 2 * t;
        *(float2*)(ao + (size_t)row0g * DM + col) =
            make_float2(o[nf][0] * inv0, o[nf][1] * inv0);
        *(float2*)(ao + (size_t)(row0g + 8) * DM + col) =
            make_float2(o[nf][2] * inv1, o[nf][3] * inv1);
    }
}

// ---------------------------------------------------------------------------
extern "C" void kernel_launch(void* const* d_in, const int* in_sizes, int n_in,
                              void* d_out, int out_size)
{
    const float* x     = (const float*)d_in[0];
    const int*   mask  = (const int*)  d_in[1];
    const float* freqs = (const float*)d_in[2];
    const float* Wqa   = (const float*)d_in[3];
    const float* qln   = (const float*)d_in[4];
    const float* Wqb   = (const float*)d_in[5];
    const float* Wkva  = (const float*)d_in[6];
    const float* kvln  = (const float*)d_in[7];
    const float* Wkvb  = (const float*)d_in[8];
    const float* Wo    = (const float*)d_in[9];
    float* out = (float*)d_out;

    float *qlat, *ckv, *kv, *ao, *qbuf;
    cudaGetSymbolAddress((void**)&qlat, g_qlat);
    cudaGetSymbolAddress((void**)&ckv,  g_ckv);
    cudaGetSymbolAddress((void**)&kv,   g_kv);
    cudaGetSymbolAddress((void**)&ao,   g_ao);
    cudaGetSymbolAddress((void**)&qbuf, g_q);

    unsigned short *xh,*xl,*qlh,*qll,*ckh,*ckl,*aoh,*aol;
    unsigned short *WqaTh,*WqaTl,*WkvaTh,*WkvaTl,*WqbTh,*WqbTl,*WkvbTh,*WkvbTl,*WoTh,*WoTl;
    cudaGetSymbolAddress((void**)&xh,  g_xh);   cudaGetSymbolAddress((void**)&xl,  g_xl);
    cudaGetSymbolAddress((void**)&qlh, g_qlh);  cudaGetSymbolAddress((void**)&qll, g_qll);
    cudaGetSymbolAddress((void**)&ckh, g_ckh);  cudaGetSymbolAddress((void**)&ckl, g_ckl);
    cudaGetSymbolAddress((void**)&aoh, g_aoh);  cudaGetSymbolAddress((void**)&aol, g_aol);
    cudaGetSymbolAddress((void**)&WqaTh, g_WqaTh);   cudaGetSymbolAddress((void**)&WqaTl, g_WqaTl);
    cudaGetSymbolAddress((void**)&WkvaTh, g_WkvaTh); cudaGetSymbolAddress((void**)&WkvaTl, g_WkvaTl);
    cudaGetSymbolAddress((void**)&WqbTh, g_WqbTh);   cudaGetSymbolAddress((void**)&WqbTl, g_WqbTl);
    cudaGetSymbolAddress((void**)&WkvbTh, g_WkvbTh); cudaGetSymbolAddress((void**)&WkvbTl, g_WkvbTl);
    cudaGetSymbolAddress((void**)&WoTh, g_WoTh);     cudaGetSymbolAddress((void**)&WoTl, g_WoTl);

    cudaFuncSetAttribute(gemm_mma, cudaFuncAttributeMaxDynamicSharedMemorySize, GEMM_SMEM);
    cudaFuncSetAttribute(flash_mma, cudaFuncAttributeMaxDynamicSharedMemorySize, FL_SMEM_BYTES);
    dim3 blk(256);

    // prep (ordered so the 6th launch = gemm1 for ncu -s 5 -c 1)
    split2<<<(SEQ * DM + 255) / 256, blk>>>(x, xh, xl, SEQ * DM);                       // 0
    transpose_split<<<dim3(QLORA / 32, DM / 32), blk>>>(Wqa, WqaTh, WqaTl, DM, QLORA);  // 1
    transpose_split<<<dim3(KVWP / 32, DM / 32), blk>>>(Wkva, WkvaTh, WkvaTl, DM, KVW);  // 2
    transpose_split<<<dim3(NQ / 32, QLORA / 32), blk>>>(Wqb, WqbTh, WqbTl, QLORA, NQ);  // 3
    transpose_split<<<dim3(NKV / 32, KVLORA / 32), blk>>>(Wkvb, WkvbTh, WkvbTl, KVLORA, NKV); // 4

    // 5: profiled launch
    gemm_mma<<<dim3(QLORA / 128, SEQ / 128), blk, GEMM_SMEM>>>(
        xh, xl, DM, WqaTh, WqaTl, DM, qlat, QLORA, QLORA, DM);
    gemm_mma<<<dim3(KVWP / 128, SEQ / 128), blk, GEMM_SMEM>>>(
        xh, xl, DM, WkvaTh, WkvaTl, DM, ckv, KVW, KVW, DM);
    rmsnorm_kernel<<<SEQ, 256>>>(qlat, qln, QLORA, QLORA);
    rmsnorm_kernel<<<SEQ, 256>>>(ckv, kvln, KVLORA, KVW);
    split2<<<(SEQ * QLORA + 255) / 256, blk>>>(qlat, qlh, qll, SEQ * QLORA);
    split2<<<(SEQ * KVW + 255) / 256, blk>>>(ckv, ckh, ckl, SEQ * KVW);
    gemm_mma<<<dim3(NQ / 128, SEQ / 128), blk, GEMM_SMEM>>>(
        qlh, qll, QLORA, WqbTh, WqbTl, QLORA, qbuf, NQ, NQ, QLORA);
    gemm_mma<<<dim3(NKV / 128, SEQ / 128), blk, GEMM_SMEM>>>(
        ckh, ckl, KVW, WkvbTh, WkvbTl, KVLORA, kv, NKV, NKV, KVLORA);

    build_qk<<<SEQ, 256>>>(freqs);
    flash_mma<<<dim3(SEQ / 128, NHEAD), blk, FL_SMEM_BYTES>>>(mask, ao);

    transpose_split<<<dim3(DM / 32, DM / 32), blk>>>(Wo, WoTh, WoTl, DM, DM);
    split2<<<(SEQ * DM + 255) / 256, blk>>>(ao, aoh, aol, SEQ * DM);
    gemm_mma<<<dim3(DM / 128, SEQ / 128), blk, GEMM_SMEM>>>(
        aoh, aol, DM, WoTh, WoTl, DM, out, DM, DM, DM);
}